// round 2
// baseline (speedup 1.0000x reference)
#include <cuda_runtime.h>
#include <cuda_bf16.h>
#include <math.h>

// DecoderLayer fwd: B=4, L=1024, D=1024, H=16, dh=64, Dff=4096, fp32.

#define BB  4
#define LL  1024
#define DD  1024
#define HH  16
#define DH  64
#define DFF 4096
#define MM  (BB*LL)   // 4096

// Scratch (allocation-free: __device__ globals)
__device__ float g_Q[MM*DD];
__device__ float g_K[MM*DD];
__device__ float g_V[MM*DD];
__device__ float g_ctx[MM*DD];
__device__ float g_X1[MM*DD];
__device__ float g_Hb[(size_t)MM*DFF];
__device__ float g_Y[MM*DD];

static __device__ __forceinline__ float selu_f(float x) {
    const float scale = 1.0507009873554804934193349852946f;
    const float alpha = 1.6732632423543772848170429916717f;
    return x > 0.f ? scale * x : scale * alpha * (__expf(x) - 1.f);
}

// ---------------------------------------------------------------------------
// SGEMM: C[M,N] = A[M,K] @ B[N,K]^T  (torch Linear layout; both K-major)
// 128x128 tile, BK=32, 256 threads, 8x8 micro-tile. All dims divide exactly.
// MODE 0: C = acc
// MODE 1: C = selu(acc + bias[n])
// MODE 2: C = acc + bias[n] + res[m*N+n]
// ---------------------------------------------------------------------------
#define TBM 128
#define TBN 128
#define TBK 32
#define SPAD 132   // 128+4: float4-aligned pad

template<int MODE>
__global__ __launch_bounds__(256)
void sgemm(const float* __restrict__ A, const float* __restrict__ B,
           float* __restrict__ C, const float* __restrict__ bias,
           const float* __restrict__ res, int M, int N, int K)
{
    __shared__ float As[TBK][SPAD];
    __shared__ float Bs[TBK][SPAD];

    const int tid = threadIdx.x;
    const int tx  = tid & 15;     // -> N
    const int ty  = tid >> 4;     // -> M
    const int m0  = blockIdx.y * TBM;
    const int n0  = blockIdx.x * TBN;

    float acc[8][8];
#pragma unroll
    for (int i = 0; i < 8; i++)
#pragma unroll
        for (int j = 0; j < 8; j++) acc[i][j] = 0.f;

    for (int k0 = 0; k0 < K; k0 += TBK) {
#pragma unroll
        for (int it = 0; it < 4; it++) {
            int idx = tid + it * 256;      // 0..1023
            int row = idx >> 3;            // 0..127
            int c4  = idx & 7;             // 0..7
            float4 a = *(const float4*)&A[(size_t)(m0 + row) * K + k0 + c4 * 4];
            As[c4*4+0][row] = a.x; As[c4*4+1][row] = a.y;
            As[c4*4+2][row] = a.z; As[c4*4+3][row] = a.w;
            float4 b = *(const float4*)&B[(size_t)(n0 + row) * K + k0 + c4 * 4];
            Bs[c4*4+0][row] = b.x; Bs[c4*4+1][row] = b.y;
            Bs[c4*4+2][row] = b.z; Bs[c4*4+3][row] = b.w;
        }
        __syncthreads();
#pragma unroll
        for (int k = 0; k < TBK; k++) {
            float ra[8], rb[8];
            *(float4*)&ra[0] = *(const float4*)&As[k][ty * 8];
            *(float4*)&ra[4] = *(const float4*)&As[k][ty * 8 + 4];
            *(float4*)&rb[0] = *(const float4*)&Bs[k][tx * 8];
            *(float4*)&rb[4] = *(const float4*)&Bs[k][tx * 8 + 4];
#pragma unroll
            for (int i = 0; i < 8; i++)
#pragma unroll
                for (int j = 0; j < 8; j++)
                    acc[i][j] = fmaf(ra[i], rb[j], acc[i][j]);
        }
        __syncthreads();
    }

#pragma unroll
    for (int i = 0; i < 8; i++) {
        const int m = m0 + ty * 8 + i;
#pragma unroll
        for (int j = 0; j < 8; j++) {
            const int n = n0 + tx * 8 + j;
            float v = acc[i][j];
            if (MODE == 1) v = selu_f(v + bias[n]);
            if (MODE == 2) v = v + bias[n] + res[(size_t)m * N + n];
            C[(size_t)m * N + n] = v;
        }
    }
}

// ---------------------------------------------------------------------------
// Flash-style causal attention. grid=(L/64, B*H), block=256 (16x16 threads).
// Each block: 64 queries x dh=64 for one (b,h). Online softmax.
// ---------------------------------------------------------------------------
__global__ __launch_bounds__(256)
void attn_kernel(const float* __restrict__ Q, const float* __restrict__ K,
                 const float* __restrict__ V, float* __restrict__ O)
{
    __shared__ float Qs[64][65];
    __shared__ float Ks[64][65];
    __shared__ float Vs[64][65];
    __shared__ float Ps[64][65];

    const int q0 = blockIdx.x * 64;
    const int bh = blockIdx.y;
    const int b  = bh >> 4;
    const int h  = bh & 15;
    const size_t base = (size_t)b * LL * DD + (size_t)h * DH;

    const int tid = threadIdx.x;
    const int tx  = tid & 15;
    const int ty  = tid >> 4;

    for (int i = tid; i < 64 * 64; i += 256) {
        int r = i >> 6, d = i & 63;
        Qs[r][d] = Q[base + (size_t)(q0 + r) * DD + d];
    }

    float m[4], l[4], o[4][4];
#pragma unroll
    for (int i = 0; i < 4; i++) {
        m[i] = -1e30f; l[i] = 0.f;
#pragma unroll
        for (int c = 0; c < 4; c++) o[i][c] = 0.f;
    }

    const int nkt = q0 / 64 + 1;
    for (int kt = 0; kt < nkt; kt++) {
        const int k0 = kt * 64;
        __syncthreads();   // previous-iter readers of Ks/Vs/Ps done (also covers Qs 1st iter)
        for (int i = tid; i < 64 * 64; i += 256) {
            int r = i >> 6, d = i & 63;
            Ks[r][d] = K[base + (size_t)(k0 + r) * DD + d];
            Vs[r][d] = V[base + (size_t)(k0 + r) * DD + d];
        }
        __syncthreads();

        float s[4][4];
#pragma unroll
        for (int i = 0; i < 4; i++)
#pragma unroll
            for (int j = 0; j < 4; j++) s[i][j] = 0.f;
        for (int d = 0; d < 64; d++) {
            float qa[4], kb[4];
#pragma unroll
            for (int i = 0; i < 4; i++) qa[i] = Qs[4 * ty + i][d];
#pragma unroll
            for (int j = 0; j < 4; j++) kb[j] = Ks[4 * tx + j][d];
#pragma unroll
            for (int i = 0; i < 4; i++)
#pragma unroll
                for (int j = 0; j < 4; j++)
                    s[i][j] = fmaf(qa[i], kb[j], s[i][j]);
        }
#pragma unroll
        for (int i = 0; i < 4; i++)
#pragma unroll
            for (int j = 0; j < 4; j++) {
                s[i][j] *= 0.125f;  // 1/sqrt(64)
                if (k0 + 4 * tx + j > q0 + 4 * ty + i) s[i][j] = -1e30f;
            }

#pragma unroll
        for (int i = 0; i < 4; i++) {
            float rm = s[i][0];
#pragma unroll
            for (int j = 1; j < 4; j++) rm = fmaxf(rm, s[i][j]);
#pragma unroll
            for (int off = 8; off; off >>= 1)
                rm = fmaxf(rm, __shfl_xor_sync(0xffffffffu, rm, off, 16));
            const float mn = fmaxf(m[i], rm);
            const float alpha = __expf(m[i] - mn);
            float rs = 0.f;
#pragma unroll
            for (int j = 0; j < 4; j++) {
                s[i][j] = __expf(s[i][j] - mn);
                rs += s[i][j];
            }
#pragma unroll
            for (int off = 8; off; off >>= 1)
                rs += __shfl_xor_sync(0xffffffffu, rs, off, 16);
            l[i] = l[i] * alpha + rs;
            m[i] = mn;
#pragma unroll
            for (int c = 0; c < 4; c++) o[i][c] *= alpha;
        }

#pragma unroll
        for (int i = 0; i < 4; i++)
#pragma unroll
            for (int j = 0; j < 4; j++)
                Ps[4 * ty + i][4 * tx + j] = s[i][j];
        __syncthreads();

        for (int k = 0; k < 64; k++) {
            float pv[4], vv[4];
#pragma unroll
            for (int i = 0; i < 4; i++) pv[i] = Ps[4 * ty + i][k];
#pragma unroll
            for (int c = 0; c < 4; c++) vv[c] = Vs[k][4 * tx + c];
#pragma unroll
            for (int i = 0; i < 4; i++)
#pragma unroll
                for (int c = 0; c < 4; c++)
                    o[i][c] = fmaf(pv[i], vv[c], o[i][c]);
        }
    }

#pragma unroll
    for (int i = 0; i < 4; i++) {
        const float inv = 1.f / l[i];
#pragma unroll
        for (int c = 0; c < 4; c++)
            O[base + (size_t)(q0 + 4 * ty + i) * DD + 4 * tx + c] = o[i][c] * inv;
    }
}

// ---------------------------------------------------------------------------
// LayerNorm over last dim (1024), optional residual. grid=4096, block=256.
// ---------------------------------------------------------------------------
__global__ __launch_bounds__(256)
void ln_kernel(const float* __restrict__ x, const float* __restrict__ add,
               const float* __restrict__ g, const float* __restrict__ bta,
               float* __restrict__ out)
{
    const int row = blockIdx.x;
    const int tid = threadIdx.x;
    const size_t off = (size_t)row * DD + tid * 4;

    float4 v = *(const float4*)&x[off];
    if (add != nullptr) {
        float4 a = *(const float4*)&add[off];
        v.x += a.x; v.y += a.y; v.z += a.z; v.w += a.w;
    }
    float s1 = v.x + v.y + v.z + v.w;
    float s2 = v.x*v.x + v.y*v.y + v.z*v.z + v.w*v.w;
#pragma unroll
    for (int o2 = 16; o2; o2 >>= 1) {
        s1 += __shfl_xor_sync(0xffffffffu, s1, o2);
        s2 += __shfl_xor_sync(0xffffffffu, s2, o2);
    }
    __shared__ float r1[8], r2[8], mb[2];
    const int lane = tid & 31, wid = tid >> 5;
    if (lane == 0) { r1[wid] = s1; r2[wid] = s2; }
    __syncthreads();
    if (tid == 0) {
        float a = 0.f, c = 0.f;
#pragma unroll
        for (int w = 0; w < 8; w++) { a += r1[w]; c += r2[w]; }
        const float mean = a * (1.f / DD);
        const float var  = c * (1.f / DD) - mean * mean;
        mb[0] = mean;
        mb[1] = rsqrtf(var + 1e-5f);
    }
    __syncthreads();
    const float mean = mb[0], rstd = mb[1];

    float4 gg = *(const float4*)&g[tid * 4];
    float4 bb = *(const float4*)&bta[tid * 4];
    float4 r;
    r.x = (v.x - mean) * rstd * gg.x + bb.x;
    r.y = (v.y - mean) * rstd * gg.y + bb.y;
    r.z = (v.z - mean) * rstd * gg.z + bb.z;
    r.w = (v.w - mean) * rstd * gg.w + bb.w;
    *(float4*)&out[off] = r;
}

// ---------------------------------------------------------------------------
extern "C" void kernel_launch(void* const* d_in, const int* in_sizes, int n_in,
                              void* d_out, int out_size)
{
    const float* X     = (const float*)d_in[0];
    const float* wq    = (const float*)d_in[1];
    const float* wk    = (const float*)d_in[2];
    const float* wv    = (const float*)d_in[3];
    const float* ln1_g = (const float*)d_in[4];
    const float* ln1_b = (const float*)d_in[5];
    const float* w1    = (const float*)d_in[6];
    const float* b1    = (const float*)d_in[7];
    const float* w2    = (const float*)d_in[8];
    const float* b2    = (const float*)d_in[9];
    const float* ln2_g = (const float*)d_in[10];
    const float* ln2_b = (const float*)d_in[11];
    float* out = (float*)d_out;

    float *pQ, *pK, *pV, *pCtx, *pX1, *pHb, *pY;
    cudaGetSymbolAddress((void**)&pQ,   g_Q);
    cudaGetSymbolAddress((void**)&pK,   g_K);
    cudaGetSymbolAddress((void**)&pV,   g_V);
    cudaGetSymbolAddress((void**)&pCtx, g_ctx);
    cudaGetSymbolAddress((void**)&pX1,  g_X1);
    cudaGetSymbolAddress((void**)&pHb,  g_Hb);
    cudaGetSymbolAddress((void**)&pY,   g_Y);

    const dim3 blk(256);
    sgemm<0><<<dim3(DD/TBN,  MM/TBM), blk>>>(X,   wq, pQ,  nullptr, nullptr, MM, DD,  DD);
    sgemm<0><<<dim3(DD/TBN,  MM/TBM), blk>>>(X,   wk, pK,  nullptr, nullptr, MM, DD,  DD);
    sgemm<0><<<dim3(DD/TBN,  MM/TBM), blk>>>(X,   wv, pV,  nullptr, nullptr, MM, DD,  DD);
    attn_kernel<<<dim3(LL/64, BB*HH), blk>>>(pQ, pK, pV, pCtx);
    ln_kernel<<<MM, blk>>>(X, pCtx, ln1_g, ln1_b, pX1);
    sgemm<1><<<dim3(DFF/TBN, MM/TBM), blk>>>(pX1, w1, pHb, b1,      nullptr, MM, DFF, DD);
    sgemm<2><<<dim3(DD/TBN,  MM/TBM), blk>>>(pHb, w2, pY,  b2,      pX1,     MM, DD,  DFF);
    ln_kernel<<<MM, blk>>>(pY, nullptr, ln2_g, ln2_b, out);
}

// round 4
// speedup vs baseline: 2.7547x; 2.7547x over previous
#include <cuda_runtime.h>
#include <cstdint>
#include <math.h>

// DecoderLayer fwd: B=4, L=1024, D=1024, H=16, dh=64, Dff=4096, fp32 I/O.
// R4: all five GEMMs via warp-level mma.sync tf32 (sm_103 plain target —
//     tcgen05 is unavailable: harness PTX targets sm_103 without the 'a' gate).

#define BB  4
#define LL  1024
#define DD  1024
#define HH  16
#define DH  64
#define DFF 4096
#define MM  (BB*LL)   // 4096

// Scratch (allocation-free: __device__ globals)
__device__ float g_Q[MM*DD];
__device__ float g_K[MM*DD];
__device__ float g_V[MM*DD];
__device__ float g_ctx[MM*DD];
__device__ float g_X1[MM*DD];
__device__ float g_Hb[(size_t)MM*DFF];
__device__ float g_Y[MM*DD];

static __device__ __forceinline__ float selu_f(float x) {
    const float scale = 1.0507009873554804934193349852946f;
    const float alpha = 1.6732632423543772848170429916717f;
    return x > 0.f ? scale * x : scale * alpha * (__expf(x) - 1.f);
}

static __device__ __forceinline__ uint32_t smem_u32(const void* p) {
    uint32_t a;
    asm("{ .reg .u64 t; cvta.to.shared.u64 t, %1; cvt.u32.u64 %0, t; }"
        : "=r"(a) : "l"(p));
    return a;
}

#define CP16(dst, src) \
    asm volatile("cp.async.cg.shared.global [%0], [%1], 16;" \
                 :: "r"((uint32_t)(dst)), "l"(src) : "memory")
#define CP_COMMIT() asm volatile("cp.async.commit_group;" ::: "memory")
#define CP_WAIT(n)  asm volatile("cp.async.wait_group %0;" :: "n"(n) : "memory")

static __device__ __forceinline__ void mma_tf32(float* c, const uint32_t* a,
                                                const uint32_t* b) {
    asm volatile(
        "mma.sync.aligned.m16n8k8.row.col.f32.tf32.tf32.f32 "
        "{%0,%1,%2,%3}, {%4,%5,%6,%7}, {%8,%9}, {%0,%1,%2,%3};"
        : "+f"(c[0]), "+f"(c[1]), "+f"(c[2]), "+f"(c[3])
        : "r"(a[0]), "r"(a[1]), "r"(a[2]), "r"(a[3]), "r"(b[0]), "r"(b[1]));
}

// ---------------------------------------------------------------------------
// tf32 mma.sync GEMM: C[M,N] = A[M,K] @ B[N,K]^T  (torch Linear layout)
// CTA 128x128, BK=32, 256 threads = 8 warps (4 M x 2 N), warp tile 32x64.
// SMEM tiles row-major [128 rows][32 k-floats = 128B], 16B chunks XOR-swizzled
// by (row&7) -> all fragment LDS conflict-free. cp.async double buffer.
// MODE 0: C = acc ; MODE 1: C = selu(acc+bias) ; MODE 2: C = acc+bias+res
// ---------------------------------------------------------------------------
#define GK        32
#define TILE_B    16384                // 128 rows * 128 B
#define BUF_BYTES (2 * TILE_B)         // A + B
#define GEMM_SMEM (2 * BUF_BYTES)      // double buffered = 65536

template<int MODE>
__global__ __launch_bounds__(256)
void gemm_mma(const float* __restrict__ A, const float* __restrict__ Bw,
              float* __restrict__ C, const float* __restrict__ bias,
              const float* __restrict__ res, int M, int N, int K)
{
    extern __shared__ char smem[];
    const uint32_t sb = smem_u32(smem);
    const int tid   = threadIdx.x;
    const int wid   = tid >> 5;
    const int lane  = tid & 31;
    const int g     = lane >> 2;       // group id 0..7
    const int tg    = lane & 3;        // thread-in-group 0..3
    const int warpM = wid & 3;         // 0..3
    const int warpN = wid >> 2;        // 0..1
    const int m0    = blockIdx.y * 128;
    const int n0    = blockIdx.x * 128;

    // stage a 128x32 chunk pair (A+B) into buffer `buf` for k-offset k0
    auto stage = [&](int buf, int k0) {
        const uint32_t ab = sb + buf * BUF_BYTES;
#pragma unroll
        for (int t = 0; t < 4; t++) {
            int idx = tid + t * 256;               // 0..1023
            int row = idx >> 3;                    // 0..127
            int c   = idx & 7;                     // 16B chunk 0..7
            uint32_t off = row * 128 + (((uint32_t)(c ^ (row & 7))) << 4);
            CP16(ab + off,          A  + (size_t)(m0 + row) * K + k0 + c * 4);
            CP16(ab + TILE_B + off, Bw + (size_t)(n0 + row) * K + k0 + c * 4);
        }
        CP_COMMIT();
    };

    float acc[2][8][4];
#pragma unroll
    for (int mt = 0; mt < 2; mt++)
#pragma unroll
        for (int nt = 0; nt < 8; nt++)
#pragma unroll
            for (int r = 0; r < 4; r++) acc[mt][nt][r] = 0.f;

    const int nch = K / GK;
    stage(0, 0);

    const int rowA  = warpM * 32 + g;     // base A row for this thread's frags
    const int colB  = warpN * 64 + g;     // base B row (n) for frags
    const int baseA = rowA * 32;          // floats
    const int baseB = colB * 32;
    const int g7    = g;                  // row&7 == g for all our rows/cols

    for (int i = 0; i < nch; i++) {
        const int buf = i & 1;
        if (i + 1 < nch) stage(buf ^ 1, (i + 1) * GK);
        if (i + 1 < nch) { CP_WAIT(1); } else { CP_WAIT(0); }
        __syncthreads();

        const uint32_t* As = (const uint32_t*)(smem + buf * BUF_BYTES);
        const uint32_t* Bs = (const uint32_t*)(smem + buf * BUF_BYTES + TILE_B);

#pragma unroll
        for (int step = 0; step < 4; step++) {
            const int c0   = step * 2;        // (kk>>2), kk = step*8
            const int off0 = (((c0    ) ^ g7) << 2) + tg;
            const int off1 = (((c0 + 1) ^ g7) << 2) + tg;

            uint32_t a[2][4];
#pragma unroll
            for (int mt = 0; mt < 2; mt++) {
                const int b0 = baseA + mt * 16 * 32;
                a[mt][0] = As[b0 + off0];
                a[mt][1] = As[b0 + 8 * 32 + off0];
                a[mt][2] = As[b0 + off1];
                a[mt][3] = As[b0 + 8 * 32 + off1];
            }
            uint32_t b[8][2];
#pragma unroll
            for (int nt = 0; nt < 8; nt++) {
                const int bb = baseB + nt * 8 * 32;
                b[nt][0] = Bs[bb + off0];
                b[nt][1] = Bs[bb + off1];
            }
#pragma unroll
            for (int mt = 0; mt < 2; mt++)
#pragma unroll
                for (int nt = 0; nt < 8; nt++)
                    mma_tf32(acc[mt][nt], a[mt], b[nt]);
        }
        __syncthreads();
    }

    // Epilogue: fragment (mt,nt): rows r0, r0+8 ; cols col, col+1
#pragma unroll
    for (int mt = 0; mt < 2; mt++) {
        const int r0 = m0 + warpM * 32 + mt * 16 + g;
#pragma unroll
        for (int nt = 0; nt < 8; nt++) {
            const int col = n0 + warpN * 64 + nt * 8 + tg * 2;
            float v0 = acc[mt][nt][0], v1 = acc[mt][nt][1];
            float v2 = acc[mt][nt][2], v3 = acc[mt][nt][3];
            if (MODE == 1) {
                v0 = selu_f(v0 + bias[col]);     v1 = selu_f(v1 + bias[col + 1]);
                v2 = selu_f(v2 + bias[col]);     v3 = selu_f(v3 + bias[col + 1]);
            }
            if (MODE == 2) {
                const float b0v = bias[col], b1v = bias[col + 1];
                v0 += b0v + res[(size_t)r0 * N + col];
                v1 += b1v + res[(size_t)r0 * N + col + 1];
                v2 += b0v + res[(size_t)(r0 + 8) * N + col];
                v3 += b1v + res[(size_t)(r0 + 8) * N + col + 1];
            }
            *(float2*)&C[(size_t)r0 * N + col]       = make_float2(v0, v1);
            *(float2*)&C[(size_t)(r0 + 8) * N + col] = make_float2(v2, v3);
        }
    }
}

// ---------------------------------------------------------------------------
// Flash-style causal attention (unchanged from R2 baseline).
// ---------------------------------------------------------------------------
__global__ __launch_bounds__(256)
void attn_kernel(const float* __restrict__ Q, const float* __restrict__ K,
                 const float* __restrict__ V, float* __restrict__ O)
{
    __shared__ float Qs[64][65];
    __shared__ float Ks[64][65];
    __shared__ float Vs[64][65];
    __shared__ float Ps[64][65];

    const int q0 = blockIdx.x * 64;
    const int bh = blockIdx.y;
    const int b  = bh >> 4;
    const int h  = bh & 15;
    const size_t base = (size_t)b * LL * DD + (size_t)h * DH;

    const int tid = threadIdx.x;
    const int tx  = tid & 15;
    const int ty  = tid >> 4;

    for (int i = tid; i < 64 * 64; i += 256) {
        int r = i >> 6, d = i & 63;
        Qs[r][d] = Q[base + (size_t)(q0 + r) * DD + d];
    }

    float m[4], l[4], o[4][4];
#pragma unroll
    for (int i = 0; i < 4; i++) {
        m[i] = -1e30f; l[i] = 0.f;
#pragma unroll
        for (int c = 0; c < 4; c++) o[i][c] = 0.f;
    }

    const int nkt = q0 / 64 + 1;
    for (int kt = 0; kt < nkt; kt++) {
        const int k0 = kt * 64;
        __syncthreads();
        for (int i = tid; i < 64 * 64; i += 256) {
            int r = i >> 6, d = i & 63;
            Ks[r][d] = K[base + (size_t)(k0 + r) * DD + d];
            Vs[r][d] = V[base + (size_t)(k0 + r) * DD + d];
        }
        __syncthreads();

        float s[4][4];
#pragma unroll
        for (int i = 0; i < 4; i++)
#pragma unroll
            for (int j = 0; j < 4; j++) s[i][j] = 0.f;
        for (int d = 0; d < 64; d++) {
            float qa[4], kb[4];
#pragma unroll
            for (int i = 0; i < 4; i++) qa[i] = Qs[4 * ty + i][d];
#pragma unroll
            for (int j = 0; j < 4; j++) kb[j] = Ks[4 * tx + j][d];
#pragma unroll
            for (int i = 0; i < 4; i++)
#pragma unroll
                for (int j = 0; j < 4; j++)
                    s[i][j] = fmaf(qa[i], kb[j], s[i][j]);
        }
#pragma unroll
        for (int i = 0; i < 4; i++)
#pragma unroll
            for (int j = 0; j < 4; j++) {
                s[i][j] *= 0.125f;
                if (k0 + 4 * tx + j > q0 + 4 * ty + i) s[i][j] = -1e30f;
            }

#pragma unroll
        for (int i = 0; i < 4; i++) {
            float rm = s[i][0];
#pragma unroll
            for (int j = 1; j < 4; j++) rm = fmaxf(rm, s[i][j]);
#pragma unroll
            for (int off = 8; off; off >>= 1)
                rm = fmaxf(rm, __shfl_xor_sync(0xffffffffu, rm, off, 16));
            const float mn = fmaxf(m[i], rm);
            const float alpha = __expf(m[i] - mn);
            float rs = 0.f;
#pragma unroll
            for (int j = 0; j < 4; j++) {
                s[i][j] = __expf(s[i][j] - mn);
                rs += s[i][j];
            }
#pragma unroll
            for (int off = 8; off; off >>= 1)
                rs += __shfl_xor_sync(0xffffffffu, rs, off, 16);
            l[i] = l[i] * alpha + rs;
            m[i] = mn;
#pragma unroll
            for (int c = 0; c < 4; c++) o[i][c] *= alpha;
        }

#pragma unroll
        for (int i = 0; i < 4; i++)
#pragma unroll
            for (int j = 0; j < 4; j++)
                Ps[4 * ty + i][4 * tx + j] = s[i][j];
        __syncthreads();

        for (int k = 0; k < 64; k++) {
            float pv[4], vv[4];
#pragma unroll
            for (int i = 0; i < 4; i++) pv[i] = Ps[4 * ty + i][k];
#pragma unroll
            for (int c = 0; c < 4; c++) vv[c] = Vs[k][4 * tx + c];
#pragma unroll
            for (int i = 0; i < 4; i++)
#pragma unroll
                for (int c = 0; c < 4; c++)
                    o[i][c] = fmaf(pv[i], vv[c], o[i][c]);
        }
    }

#pragma unroll
    for (int i = 0; i < 4; i++) {
        const float inv = 1.f / l[i];
#pragma unroll
        for (int c = 0; c < 4; c++)
            O[base + (size_t)(q0 + 4 * ty + i) * DD + 4 * tx + c] = o[i][c] * inv;
    }
}

// ---------------------------------------------------------------------------
// LayerNorm over last dim (1024), optional residual (unchanged).
// ---------------------------------------------------------------------------
__global__ __launch_bounds__(256)
void ln_kernel(const float* __restrict__ x, const float* __restrict__ add,
               const float* __restrict__ g, const float* __restrict__ bta,
               float* __restrict__ out)
{
    const int row = blockIdx.x;
    const int tid = threadIdx.x;
    const size_t off = (size_t)row * DD + tid * 4;

    float4 v = *(const float4*)&x[off];
    if (add != nullptr) {
        float4 a = *(const float4*)&add[off];
        v.x += a.x; v.y += a.y; v.z += a.z; v.w += a.w;
    }
    float s1 = v.x + v.y + v.z + v.w;
    float s2 = v.x*v.x + v.y*v.y + v.z*v.z + v.w*v.w;
#pragma unroll
    for (int o2 = 16; o2; o2 >>= 1) {
        s1 += __shfl_xor_sync(0xffffffffu, s1, o2);
        s2 += __shfl_xor_sync(0xffffffffu, s2, o2);
    }
    __shared__ float r1[8], r2[8], mb[2];
    const int lane = tid & 31, wd = tid >> 5;
    if (lane == 0) { r1[wd] = s1; r2[wd] = s2; }
    __syncthreads();
    if (tid == 0) {
        float a = 0.f, c = 0.f;
#pragma unroll
        for (int w = 0; w < 8; w++) { a += r1[w]; c += r2[w]; }
        const float mean = a * (1.f / DD);
        const float var  = c * (1.f / DD) - mean * mean;
        mb[0] = mean;
        mb[1] = rsqrtf(var + 1e-5f);
    }
    __syncthreads();
    const float mean = mb[0], rstd = mb[1];

    float4 gg = *(const float4*)&g[tid * 4];
    float4 bb = *(const float4*)&bta[tid * 4];
    float4 r;
    r.x = (v.x - mean) * rstd * gg.x + bb.x;
    r.y = (v.y - mean) * rstd * gg.y + bb.y;
    r.z = (v.z - mean) * rstd * gg.z + bb.z;
    r.w = (v.w - mean) * rstd * gg.w + bb.w;
    *(float4*)&out[off] = r;
}

// ---------------------------------------------------------------------------
extern "C" void kernel_launch(void* const* d_in, const int* in_sizes, int n_in,
                              void* d_out, int out_size)
{
    const float* X     = (const float*)d_in[0];
    const float* wq    = (const float*)d_in[1];
    const float* wk    = (const float*)d_in[2];
    const float* wv    = (const float*)d_in[3];
    const float* ln1_g = (const float*)d_in[4];
    const float* ln1_b = (const float*)d_in[5];
    const float* w1    = (const float*)d_in[6];
    const float* b1    = (const float*)d_in[7];
    const float* w2    = (const float*)d_in[8];
    const float* b2    = (const float*)d_in[9];
    const float* ln2_g = (const float*)d_in[10];
    const float* ln2_b = (const float*)d_in[11];
    float* out = (float*)d_out;

    float *pQ, *pK, *pV, *pCtx, *pX1, *pHb, *pY;
    cudaGetSymbolAddress((void**)&pQ,   g_Q);
    cudaGetSymbolAddress((void**)&pK,   g_K);
    cudaGetSymbolAddress((void**)&pV,   g_V);
    cudaGetSymbolAddress((void**)&pCtx, g_ctx);
    cudaGetSymbolAddress((void**)&pX1,  g_X1);
    cudaGetSymbolAddress((void**)&pHb,  g_Hb);
    cudaGetSymbolAddress((void**)&pY,   g_Y);

    cudaFuncSetAttribute(gemm_mma<0>, cudaFuncAttributeMaxDynamicSharedMemorySize, GEMM_SMEM);
    cudaFuncSetAttribute(gemm_mma<1>, cudaFuncAttributeMaxDynamicSharedMemorySize, GEMM_SMEM);
    cudaFuncSetAttribute(gemm_mma<2>, cudaFuncAttributeMaxDynamicSharedMemorySize, GEMM_SMEM);

    const dim3 blk(256);
    gemm_mma<0><<<dim3(DD/128,  MM/128), blk, GEMM_SMEM>>>(X,   wq, pQ,  nullptr, nullptr, MM, DD,  DD);
    gemm_mma<0><<<dim3(DD/128,  MM/128), blk, GEMM_SMEM>>>(X,   wk, pK,  nullptr, nullptr, MM, DD,  DD);
    gemm_mma<0><<<dim3(DD/128,  MM/128), blk, GEMM_SMEM>>>(X,   wv, pV,  nullptr, nullptr, MM, DD,  DD);
    attn_kernel<<<dim3(LL/64, BB*HH), 256>>>(pQ, pK, pV, pCtx);
    ln_kernel<<<MM, 256>>>(X, pCtx, ln1_g, ln1_b, pX1);
    gemm_mma<1><<<dim3(DFF/128, MM/128), blk, GEMM_SMEM>>>(pX1, w1, pHb, b1,      nullptr, MM, DFF, DD);
    gemm_mma<2><<<dim3(DD/128,  MM/128), blk, GEMM_SMEM>>>(pHb, w2, pY,  b2,      pX1,     MM, DD,  DFF);
    ln_kernel<<<MM, 256>>>(pY, nullptr, ln2_g, ln2_b, out);
}

// round 6
// speedup vs baseline: 3.6337x; 1.3191x over previous
#include <cuda_runtime.h>
#include <cstdint>
#include <math.h>

// DecoderLayer fwd: B=4, L=1024, D=1024, H=16, dh=64, Dff=4096, fp32 I/O.
// R5: GEMMs unchanged (mma.sync tf32). Attention rewritten on tensor cores:
//     QK^T via 3xTF32 split (near-fp32 scores), PV via plain tf32 mma.

#define BB  4
#define LL  1024
#define DD  1024
#define HH  16
#define DH  64
#define DFF 4096
#define MM  (BB*LL)   // 4096

// Scratch (allocation-free: __device__ globals)
__device__ float g_Q[MM*DD];
__device__ float g_K[MM*DD];
__device__ float g_V[MM*DD];
__device__ float g_ctx[MM*DD];
__device__ float g_X1[MM*DD];
__device__ float g_Hb[(size_t)MM*DFF];
__device__ float g_Y[MM*DD];

static __device__ __forceinline__ float selu_f(float x) {
    const float scale = 1.0507009873554804934193349852946f;
    const float alpha = 1.6732632423543772848170429916717f;
    return x > 0.f ? scale * x : scale * alpha * (__expf(x) - 1.f);
}

static __device__ __forceinline__ uint32_t smem_u32(const void* p) {
    uint32_t a;
    asm("{ .reg .u64 t; cvta.to.shared.u64 t, %1; cvt.u32.u64 %0, t; }"
        : "=r"(a) : "l"(p));
    return a;
}

#define CP16(dst, src) \
    asm volatile("cp.async.cg.shared.global [%0], [%1], 16;" \
                 :: "r"((uint32_t)(dst)), "l"(src) : "memory")
#define CP_COMMIT() asm volatile("cp.async.commit_group;" ::: "memory")
#define CP_WAIT(n)  asm volatile("cp.async.wait_group %0;" :: "n"(n) : "memory")

static __device__ __forceinline__ void mma_tf32(float* c, const uint32_t* a,
                                                const uint32_t* b) {
    asm volatile(
        "mma.sync.aligned.m16n8k8.row.col.f32.tf32.tf32.f32 "
        "{%0,%1,%2,%3}, {%4,%5,%6,%7}, {%8,%9}, {%0,%1,%2,%3};"
        : "+f"(c[0]), "+f"(c[1]), "+f"(c[2]), "+f"(c[3])
        : "r"(a[0]), "r"(a[1]), "r"(a[2]), "r"(a[3]), "r"(b[0]), "r"(b[1]));
}

static __device__ __forceinline__ float tf32r(float x) {
    uint32_t u;
    asm("cvt.rna.tf32.f32 %0, %1;" : "=r"(u) : "f"(x));
    return __uint_as_float(u);
}

// ---------------------------------------------------------------------------
// tf32 mma.sync GEMM (unchanged from R4): C[M,N] = A[M,K] @ B[N,K]^T
// ---------------------------------------------------------------------------
#define GK        32
#define TILE_B    16384
#define BUF_BYTES (2 * TILE_B)
#define GEMM_SMEM (2 * BUF_BYTES)

template<int MODE>
__global__ __launch_bounds__(256)
void gemm_mma(const float* __restrict__ A, const float* __restrict__ Bw,
              float* __restrict__ C, const float* __restrict__ bias,
              const float* __restrict__ res, int M, int N, int K)
{
    extern __shared__ char smem[];
    const uint32_t sb = smem_u32(smem);
    const int tid   = threadIdx.x;
    const int wid   = tid >> 5;
    const int lane  = tid & 31;
    const int g     = lane >> 2;
    const int tg    = lane & 3;
    const int warpM = wid & 3;
    const int warpN = wid >> 2;
    const int m0    = blockIdx.y * 128;
    const int n0    = blockIdx.x * 128;

    auto stage = [&](int buf, int k0) {
        const uint32_t ab = sb + buf * BUF_BYTES;
#pragma unroll
        for (int t = 0; t < 4; t++) {
            int idx = tid + t * 256;
            int row = idx >> 3;
            int c   = idx & 7;
            uint32_t off = row * 128 + (((uint32_t)(c ^ (row & 7))) << 4);
            CP16(ab + off,          A  + (size_t)(m0 + row) * K + k0 + c * 4);
            CP16(ab + TILE_B + off, Bw + (size_t)(n0 + row) * K + k0 + c * 4);
        }
        CP_COMMIT();
    };

    float acc[2][8][4];
#pragma unroll
    for (int mt = 0; mt < 2; mt++)
#pragma unroll
        for (int nt = 0; nt < 8; nt++)
#pragma unroll
            for (int r = 0; r < 4; r++) acc[mt][nt][r] = 0.f;

    const int nch = K / GK;
    stage(0, 0);

    const int rowA  = warpM * 32 + g;
    const int colB  = warpN * 64 + g;
    const int baseA = rowA * 32;
    const int baseB = colB * 32;
    const int g7    = g;

    for (int i = 0; i < nch; i++) {
        const int buf = i & 1;
        if (i + 1 < nch) stage(buf ^ 1, (i + 1) * GK);
        if (i + 1 < nch) { CP_WAIT(1); } else { CP_WAIT(0); }
        __syncthreads();

        const uint32_t* As = (const uint32_t*)(smem + buf * BUF_BYTES);
        const uint32_t* Bs = (const uint32_t*)(smem + buf * BUF_BYTES + TILE_B);

#pragma unroll
        for (int step = 0; step < 4; step++) {
            const int c0   = step * 2;
            const int off0 = (((c0    ) ^ g7) << 2) + tg;
            const int off1 = (((c0 + 1) ^ g7) << 2) + tg;

            uint32_t a[2][4];
#pragma unroll
            for (int mt = 0; mt < 2; mt++) {
                const int b0 = baseA + mt * 16 * 32;
                a[mt][0] = As[b0 + off0];
                a[mt][1] = As[b0 + 8 * 32 + off0];
                a[mt][2] = As[b0 + off1];
                a[mt][3] = As[b0 + 8 * 32 + off1];
            }
            uint32_t b[8][2];
#pragma unroll
            for (int nt = 0; nt < 8; nt++) {
                const int bb = baseB + nt * 8 * 32;
                b[nt][0] = Bs[bb + off0];
                b[nt][1] = Bs[bb + off1];
            }
#pragma unroll
            for (int mt = 0; mt < 2; mt++)
#pragma unroll
                for (int nt = 0; nt < 8; nt++)
                    mma_tf32(acc[mt][nt], a[mt], b[nt]);
        }
        __syncthreads();
    }

#pragma unroll
    for (int mt = 0; mt < 2; mt++) {
        const int r0 = m0 + warpM * 32 + mt * 16 + g;
#pragma unroll
        for (int nt = 0; nt < 8; nt++) {
            const int col = n0 + warpN * 64 + nt * 8 + tg * 2;
            float v0 = acc[mt][nt][0], v1 = acc[mt][nt][1];
            float v2 = acc[mt][nt][2], v3 = acc[mt][nt][3];
            if (MODE == 1) {
                v0 = selu_f(v0 + bias[col]);     v1 = selu_f(v1 + bias[col + 1]);
                v2 = selu_f(v2 + bias[col]);     v3 = selu_f(v3 + bias[col + 1]);
            }
            if (MODE == 2) {
                const float b0v = bias[col], b1v = bias[col + 1];
                v0 += b0v + res[(size_t)r0 * N + col];
                v1 += b1v + res[(size_t)r0 * N + col + 1];
                v2 += b0v + res[(size_t)(r0 + 8) * N + col];
                v3 += b1v + res[(size_t)(r0 + 8) * N + col + 1];
            }
            *(float2*)&C[(size_t)r0 * N + col]       = make_float2(v0, v1);
            *(float2*)&C[(size_t)(r0 + 8) * N + col] = make_float2(v2, v3);
        }
    }
}

// ---------------------------------------------------------------------------
// Tensor-core flash attention. grid=(16, B*H), block=128 (4 warps).
// Block: 64 q-rows of one head; k-tiles of 64. Warp w owns q-rows 16w..16w+15.
// QK^T: 3xTF32 split (Qh*Kh + Qh*Kl + Ql*Kh) -> near-fp32 scores.
// PV:   plain tf32; P converted S-frag -> A-frag via quad shuffles.
// SMEM strides: Q/K 68 (bank = 4g+tg, conflict-free), V 72 (8tg+g).
// ---------------------------------------------------------------------------
#define SQK 68
#define SV  72
#define ATT_SMEM ((4*64*SQK + 64*SV) * 4)   // 88064 B

__global__ __launch_bounds__(128)
void attn_tc(const float* __restrict__ Q, const float* __restrict__ K,
             const float* __restrict__ V, float* __restrict__ O)
{
    extern __shared__ float sm[];
    float* Qh = sm;
    float* Ql = Qh + 64*SQK;
    float* Kh = Ql + 64*SQK;
    float* Kl = Kh + 64*SQK;
    float* Vs = Kl + 64*SQK;

    const int qb = (int)gridDim.x - 1 - (int)blockIdx.x;  // heavy blocks first
    const int q0 = qb * 64;
    const int bh = blockIdx.y;
    const int b  = bh >> 4;
    const int h  = bh & 15;
    const size_t base = (size_t)b * LL * DD + (size_t)h * DH;

    const int tid  = threadIdx.x;
    const int w    = tid >> 5;
    const int lane = tid & 31;
    const int g    = lane >> 2;
    const int tg   = lane & 3;
    const int qw   = w * 16;

    // Load Q tile (scaled by 1/sqrt(dh)=0.125), split into tf32 hi/lo.
#pragma unroll
    for (int i = 0; i < 8; i++) {
        int idx = tid + i * 128;
        int r = idx >> 4, c4 = (idx & 15) * 4;
        float4 v = *(const float4*)&Q[base + (size_t)(q0 + r) * DD + c4];
        v.x *= 0.125f; v.y *= 0.125f; v.z *= 0.125f; v.w *= 0.125f;
        float4 hi, lo;
        hi.x = tf32r(v.x); lo.x = v.x - hi.x;
        hi.y = tf32r(v.y); lo.y = v.y - hi.y;
        hi.z = tf32r(v.z); lo.z = v.z - hi.z;
        hi.w = tf32r(v.w); lo.w = v.w - hi.w;
        *(float4*)&Qh[r * SQK + c4] = hi;
        *(float4*)&Ql[r * SQK + c4] = lo;
    }

    float m0r = -1e30f, m1r = -1e30f, l0r = 0.f, l1r = 0.f;
    float oacc[8][4];
#pragma unroll
    for (int nb = 0; nb < 8; nb++)
#pragma unroll
        for (int r = 0; r < 4; r++) oacc[nb][r] = 0.f;

    const int ntile = qb + 1;
    for (int kt = 0; kt < ntile; kt++) {
        const int k0 = kt * 64;
        __syncthreads();  // prior readers of Kh/Kl/Vs done; covers Q stores on kt=0
#pragma unroll
        for (int i = 0; i < 8; i++) {
            int idx = tid + i * 128;
            int r = idx >> 4, c4 = (idx & 15) * 4;
            float4 kv = *(const float4*)&K[base + (size_t)(k0 + r) * DD + c4];
            float4 hi, lo;
            hi.x = tf32r(kv.x); lo.x = kv.x - hi.x;
            hi.y = tf32r(kv.y); lo.y = kv.y - hi.y;
            hi.z = tf32r(kv.z); lo.z = kv.z - hi.z;
            hi.w = tf32r(kv.w); lo.w = kv.w - hi.w;
            *(float4*)&Kh[r * SQK + c4] = hi;
            *(float4*)&Kl[r * SQK + c4] = lo;
            float4 vv = *(const float4*)&V[base + (size_t)(k0 + r) * DD + c4];
            *(float4*)&Vs[r * SV + c4] = vv;
        }
        __syncthreads();

        // ---- S = (Q*0.125) @ K^T  (3xTF32) ----
        float sacc[8][4];
#pragma unroll
        for (int nb = 0; nb < 8; nb++)
#pragma unroll
            for (int r = 0; r < 4; r++) sacc[nb][r] = 0.f;

#pragma unroll
        for (int ks = 0; ks < 8; ks++) {
            const int d0 = ks * 8 + tg;
            uint32_t ah[4], al[4];
            ah[0] = __float_as_uint(Qh[(qw + g    ) * SQK + d0    ]);
            ah[1] = __float_as_uint(Qh[(qw + g + 8) * SQK + d0    ]);
            ah[2] = __float_as_uint(Qh[(qw + g    ) * SQK + d0 + 4]);
            ah[3] = __float_as_uint(Qh[(qw + g + 8) * SQK + d0 + 4]);
            al[0] = __float_as_uint(Ql[(qw + g    ) * SQK + d0    ]);
            al[1] = __float_as_uint(Ql[(qw + g + 8) * SQK + d0    ]);
            al[2] = __float_as_uint(Ql[(qw + g    ) * SQK + d0 + 4]);
            al[3] = __float_as_uint(Ql[(qw + g + 8) * SQK + d0 + 4]);
#pragma unroll
            for (int nb = 0; nb < 8; nb++) {
                uint32_t bh2[2], bl2[2];
                bh2[0] = __float_as_uint(Kh[(nb * 8 + g) * SQK + d0    ]);
                bh2[1] = __float_as_uint(Kh[(nb * 8 + g) * SQK + d0 + 4]);
                bl2[0] = __float_as_uint(Kl[(nb * 8 + g) * SQK + d0    ]);
                bl2[1] = __float_as_uint(Kl[(nb * 8 + g) * SQK + d0 + 4]);
                mma_tf32(sacc[nb], ah, bh2);
                mma_tf32(sacc[nb], ah, bl2);
                mma_tf32(sacc[nb], al, bh2);
            }
        }

        // ---- causal mask (diagonal tile only) ----
        if (k0 == q0) {
#pragma unroll
            for (int nb = 0; nb < 8; nb++) {
                const int col = nb * 8 + 2 * tg;
                const int r0 = qw + g, r1 = r0 + 8;
                if (col     > r0) sacc[nb][0] = -1e30f;
                if (col + 1 > r0) sacc[nb][1] = -1e30f;
                if (col     > r1) sacc[nb][2] = -1e30f;
                if (col + 1 > r1) sacc[nb][3] = -1e30f;
            }
        }

        // ---- online softmax (rows g and g+8; quad = 4 lanes sharing g) ----
        float mx0 = -1e30f, mx1 = -1e30f;
#pragma unroll
        for (int nb = 0; nb < 8; nb++) {
            mx0 = fmaxf(mx0, fmaxf(sacc[nb][0], sacc[nb][1]));
            mx1 = fmaxf(mx1, fmaxf(sacc[nb][2], sacc[nb][3]));
        }
        mx0 = fmaxf(mx0, __shfl_xor_sync(0xffffffffu, mx0, 1));
        mx0 = fmaxf(mx0, __shfl_xor_sync(0xffffffffu, mx0, 2));
        mx1 = fmaxf(mx1, __shfl_xor_sync(0xffffffffu, mx1, 1));
        mx1 = fmaxf(mx1, __shfl_xor_sync(0xffffffffu, mx1, 2));

        const float nm0 = fmaxf(m0r, mx0), nm1 = fmaxf(m1r, mx1);
        const float al0 = __expf(m0r - nm0), al1 = __expf(m1r - nm1);
        float rs0 = 0.f, rs1 = 0.f;
#pragma unroll
        for (int nb = 0; nb < 8; nb++) {
            sacc[nb][0] = __expf(sacc[nb][0] - nm0);
            sacc[nb][1] = __expf(sacc[nb][1] - nm0);
            sacc[nb][2] = __expf(sacc[nb][2] - nm1);
            sacc[nb][3] = __expf(sacc[nb][3] - nm1);
            rs0 += sacc[nb][0] + sacc[nb][1];
            rs1 += sacc[nb][2] + sacc[nb][3];
        }
        rs0 += __shfl_xor_sync(0xffffffffu, rs0, 1);
        rs0 += __shfl_xor_sync(0xffffffffu, rs0, 2);
        rs1 += __shfl_xor_sync(0xffffffffu, rs1, 1);
        rs1 += __shfl_xor_sync(0xffffffffu, rs1, 2);
        l0r = l0r * al0 + rs0;
        l1r = l1r * al1 + rs1;
        m0r = nm0; m1r = nm1;
#pragma unroll
        for (int nb = 0; nb < 8; nb++) {
            oacc[nb][0] *= al0; oacc[nb][1] *= al0;
            oacc[nb][2] *= al1; oacc[nb][3] *= al1;
        }

        // ---- O += P @ V  (P: S-frag -> A-frag via quad shuffles) ----
#pragma unroll
        for (int ks2 = 0; ks2 < 8; ks2++) {
            const int sA = (lane & 28) | (tg >> 1);
            const int sB = sA + 2;
            const float q0v = __shfl_sync(0xffffffffu, sacc[ks2][0], sA);
            const float q1v = __shfl_sync(0xffffffffu, sacc[ks2][1], sA);
            const float q2v = __shfl_sync(0xffffffffu, sacc[ks2][2], sA);
            const float q3v = __shfl_sync(0xffffffffu, sacc[ks2][3], sA);
            const float r0v = __shfl_sync(0xffffffffu, sacc[ks2][0], sB);
            const float r1v = __shfl_sync(0xffffffffu, sacc[ks2][1], sB);
            const float r2v = __shfl_sync(0xffffffffu, sacc[ks2][2], sB);
            const float r3v = __shfl_sync(0xffffffffu, sacc[ks2][3], sB);
            const bool oddc = (tg & 1);
            uint32_t aP[4];
            aP[0] = __float_as_uint(oddc ? q1v : q0v);  // (g,    tg)
            aP[1] = __float_as_uint(oddc ? q3v : q2v);  // (g+8,  tg)
            aP[2] = __float_as_uint(oddc ? r1v : r0v);  // (g,    tg+4)
            aP[3] = __float_as_uint(oddc ? r3v : r2v);  // (g+8,  tg+4)
#pragma unroll
            for (int nb2 = 0; nb2 < 8; nb2++) {
                uint32_t bV[2];
                bV[0] = __float_as_uint(Vs[(ks2 * 8 + tg    ) * SV + nb2 * 8 + g]);
                bV[1] = __float_as_uint(Vs[(ks2 * 8 + tg + 4) * SV + nb2 * 8 + g]);
                mma_tf32(oacc[nb2], aP, bV);
            }
        }
    }

    // ---- epilogue ----
    const float inv0 = 1.f / l0r, inv1 = 1.f / l1r;
    const int r0 = q0 + qw + g, r1 = r0 + 8;
#pragma unroll
    for (int nb = 0; nb < 8; nb++) {
        const int c = nb * 8 + tg * 2;
        *(float2*)&O[base + (size_t)r0 * DD + c] =
            make_float2(oacc[nb][0] * inv0, oacc[nb][1] * inv0);
        *(float2*)&O[base + (size_t)r1 * DD + c] =
            make_float2(oacc[nb][2] * inv1, oacc[nb][3] * inv1);
    }
}

// ---------------------------------------------------------------------------
// LayerNorm over last dim (1024), optional residual (unchanged).
// ---------------------------------------------------------------------------
__global__ __launch_bounds__(256)
void ln_kernel(const float* __restrict__ x, const float* __restrict__ add,
               const float* __restrict__ g, const float* __restrict__ bta,
               float* __restrict__ out)
{
    const int row = blockIdx.x;
    const int tid = threadIdx.x;
    const size_t off = (size_t)row * DD + tid * 4;

    float4 v = *(const float4*)&x[off];
    if (add != nullptr) {
        float4 a = *(const float4*)&add[off];
        v.x += a.x; v.y += a.y; v.z += a.z; v.w += a.w;
    }
    float s1 = v.x + v.y + v.z + v.w;
    float s2 = v.x*v.x + v.y*v.y + v.z*v.z + v.w*v.w;
#pragma unroll
    for (int o2 = 16; o2; o2 >>= 1) {
        s1 += __shfl_xor_sync(0xffffffffu, s1, o2);
        s2 += __shfl_xor_sync(0xffffffffu, s2, o2);
    }
    __shared__ float r1[8], r2[8], mb[2];
    const int lane = tid & 31, wd = tid >> 5;
    if (lane == 0) { r1[wd] = s1; r2[wd] = s2; }
    __syncthreads();
    if (tid == 0) {
        float a = 0.f, c = 0.f;
#pragma unroll
        for (int w = 0; w < 8; w++) { a += r1[w]; c += r2[w]; }
        const float mean = a * (1.f / DD);
        const float var  = c * (1.f / DD) - mean * mean;
        mb[0] = mean;
        mb[1] = rsqrtf(var + 1e-5f);
    }
    __syncthreads();
    const float mean = mb[0], rstd = mb[1];

    float4 gg = *(const float4*)&g[tid * 4];
    float4 bb = *(const float4*)&bta[tid * 4];
    float4 r;
    r.x = (v.x - mean) * rstd * gg.x + bb.x;
    r.y = (v.y - mean) * rstd * gg.y + bb.y;
    r.z = (v.z - mean) * rstd * gg.z + bb.z;
    r.w = (v.w - mean) * rstd * gg.w + bb.w;
    *(float4*)&out[off] = r;
}

// ---------------------------------------------------------------------------
extern "C" void kernel_launch(void* const* d_in, const int* in_sizes, int n_in,
                              void* d_out, int out_size)
{
    const float* X     = (const float*)d_in[0];
    const float* wq    = (const float*)d_in[1];
    const float* wk    = (const float*)d_in[2];
    const float* wv    = (const float*)d_in[3];
    const float* ln1_g = (const float*)d_in[4];
    const float* ln1_b = (const float*)d_in[5];
    const float* w1    = (const float*)d_in[6];
    const float* b1    = (const float*)d_in[7];
    const float* w2    = (const float*)d_in[8];
    const float* b2    = (const float*)d_in[9];
    const float* ln2_g = (const float*)d_in[10];
    const float* ln2_b = (const float*)d_in[11];
    float* out = (float*)d_out;

    float *pQ, *pK, *pV, *pCtx, *pX1, *pHb, *pY;
    cudaGetSymbolAddress((void**)&pQ,   g_Q);
    cudaGetSymbolAddress((void**)&pK,   g_K);
    cudaGetSymbolAddress((void**)&pV,   g_V);
    cudaGetSymbolAddress((void**)&pCtx, g_ctx);
    cudaGetSymbolAddress((void**)&pX1,  g_X1);
    cudaGetSymbolAddress((void**)&pHb,  g_Hb);
    cudaGetSymbolAddress((void**)&pY,   g_Y);

    cudaFuncSetAttribute(gemm_mma<0>, cudaFuncAttributeMaxDynamicSharedMemorySize, GEMM_SMEM);
    cudaFuncSetAttribute(gemm_mma<1>, cudaFuncAttributeMaxDynamicSharedMemorySize, GEMM_SMEM);
    cudaFuncSetAttribute(gemm_mma<2>, cudaFuncAttributeMaxDynamicSharedMemorySize, GEMM_SMEM);
    cudaFuncSetAttribute(attn_tc,     cudaFuncAttributeMaxDynamicSharedMemorySize, ATT_SMEM);

    const dim3 blk(256);
    gemm_mma<0><<<dim3(DD/128,  MM/128), blk, GEMM_SMEM>>>(X,   wq, pQ,  nullptr, nullptr, MM, DD,  DD);
    gemm_mma<0><<<dim3(DD/128,  MM/128), blk, GEMM_SMEM>>>(X,   wk, pK,  nullptr, nullptr, MM, DD,  DD);
    gemm_mma<0><<<dim3(DD/128,  MM/128), blk, GEMM_SMEM>>>(X,   wv, pV,  nullptr, nullptr, MM, DD,  DD);
    attn_tc<<<dim3(LL/64, BB*HH), 128, ATT_SMEM>>>(pQ, pK, pV, pCtx);
    ln_kernel<<<MM, 256>>>(X, pCtx, ln1_g, ln1_b, pX1);
    gemm_mma<1><<<dim3(DFF/128, MM/128), blk, GEMM_SMEM>>>(pX1, w1, pHb, b1,      nullptr, MM, DFF, DD);
    gemm_mma<2><<<dim3(DD/128,  MM/128), blk, GEMM_SMEM>>>(pHb, w2, pY,  b2,      pX1,     MM, DD,  DFF);
    ln_kernel<<<MM, 256>>>(pY, nullptr, ln2_g, ln2_b, out);
}

// round 7
// speedup vs baseline: 3.9227x; 1.0795x over previous
#include <cuda_runtime.h>
#include <cstdint>
#include <math.h>

// DecoderLayer fwd: B=4, L=1024, D=1024, H=16, dh=64, Dff=4096, fp32 I/O.
// R6: GEMM rework — 64x64 warp tiles (LDS:MMA 1.5->1.0), 3-stage cp.async,
//     QKV fused into one launch. Attention/LN unchanged from R5.

#define BB  4
#define LL  1024
#define DD  1024
#define HH  16
#define DH  64
#define DFF 4096
#define MM  (BB*LL)   // 4096

// Scratch (allocation-free: __device__ globals)
__device__ float g_Q[MM*DD];
__device__ float g_K[MM*DD];
__device__ float g_V[MM*DD];
__device__ float g_ctx[MM*DD];
__device__ float g_X1[MM*DD];
__device__ float g_Hb[(size_t)MM*DFF];
__device__ float g_Y[MM*DD];

static __device__ __forceinline__ float selu_f(float x) {
    const float scale = 1.0507009873554804934193349852946f;
    const float alpha = 1.6732632423543772848170429916717f;
    return x > 0.f ? scale * x : scale * alpha * (__expf(x) - 1.f);
}

static __device__ __forceinline__ uint32_t smem_u32(const void* p) {
    uint32_t a;
    asm("{ .reg .u64 t; cvta.to.shared.u64 t, %1; cvt.u32.u64 %0, t; }"
        : "=r"(a) : "l"(p));
    return a;
}

#define CP16(dst, src) \
    asm volatile("cp.async.cg.shared.global [%0], [%1], 16;" \
                 :: "r"((uint32_t)(dst)), "l"(src) : "memory")
#define CP_COMMIT() asm volatile("cp.async.commit_group;" ::: "memory")
#define CP_WAIT(n)  asm volatile("cp.async.wait_group %0;" :: "n"(n) : "memory")

static __device__ __forceinline__ void mma_tf32(float* c, const uint32_t* a,
                                                const uint32_t* b) {
    asm volatile(
        "mma.sync.aligned.m16n8k8.row.col.f32.tf32.tf32.f32 "
        "{%0,%1,%2,%3}, {%4,%5,%6,%7}, {%8,%9}, {%0,%1,%2,%3};"
        : "+f"(c[0]), "+f"(c[1]), "+f"(c[2]), "+f"(c[3])
        : "r"(a[0]), "r"(a[1]), "r"(a[2]), "r"(a[3]), "r"(b[0]), "r"(b[1]));
}

static __device__ __forceinline__ float tf32r(float x) {
    uint32_t u;
    asm("cvt.rna.tf32.f32 %0, %1;" : "=r"(u) : "f"(x));
    return __uint_as_float(u);
}

// ---------------------------------------------------------------------------
// tf32 mma.sync GEMM: C[M,N] = A[M,K] @ B[N,K]^T  (torch Linear layout)
// CTA 128x128, BK=32, 128 threads = 4 warps (2Mx2N), warp tile 64x64.
// 3-stage cp.async pipeline. 16B chunks XOR(row&7)-swizzled; all fragment
// LDS conflict-free (bank = 4*(c^g)+tg covers 0..31).
// MODE 1: C = selu(acc+bias) ; MODE 2: C = acc+bias+res ;
// MODE 3: QKV — blockIdx.z selects (B0,C0)/(B1,C1)/(B2,C2), plain store.
// ---------------------------------------------------------------------------
#define GK        32
#define TILE_B    16384                 // 128 rows * 32 floats * 4B
#define BUF_BYTES (2 * TILE_B)          // A + B per stage
#define NSTAGE    3
#define GEMM_SMEM (NSTAGE * BUF_BYTES)  // 98304

template<int MODE>
__global__ __launch_bounds__(128)
void gemm_mma(const float* __restrict__ A,
              const float* __restrict__ B0, const float* __restrict__ B1,
              const float* __restrict__ B2,
              float* __restrict__ C0, float* __restrict__ C1,
              float* __restrict__ C2,
              const float* __restrict__ bias, const float* __restrict__ res,
              int M, int N, int K)
{
    extern __shared__ char smem[];
    const uint32_t sb = smem_u32(smem);
    const int tid  = threadIdx.x;
    const int wid  = tid >> 5;
    const int lane = tid & 31;
    const int g    = lane >> 2;
    const int tg   = lane & 3;
    const int wm   = wid & 1;          // 2 warps in M
    const int wn   = wid >> 1;         // 2 warps in N
    const int m0   = blockIdx.y * 128;
    const int n0   = blockIdx.x * 128;

    const float* Bw = B0;
    float*       C  = C0;
    if (MODE == 3) {
        if (blockIdx.z == 1)      { Bw = B1; C = C1; }
        else if (blockIdx.z == 2) { Bw = B2; C = C2; }
    }

    auto stage = [&](int s, int k0) {
        const uint32_t ab = sb + s * BUF_BYTES;
#pragma unroll
        for (int t = 0; t < 8; t++) {
            int idx = tid + t * 128;               // 0..1023
            int row = idx >> 3;                    // 0..127
            int c   = idx & 7;                     // 16B chunk
            uint32_t off = row * 128 + (((uint32_t)(c ^ (row & 7))) << 4);
            CP16(ab + off,          A  + (size_t)(m0 + row) * K + k0 + c * 4);
            CP16(ab + TILE_B + off, Bw + (size_t)(n0 + row) * K + k0 + c * 4);
        }
        CP_COMMIT();
    };

    float acc[4][8][4];
#pragma unroll
    for (int mt = 0; mt < 4; mt++)
#pragma unroll
        for (int nt = 0; nt < 8; nt++)
#pragma unroll
            for (int r = 0; r < 4; r++) acc[mt][nt][r] = 0.f;

    const int nch = K / GK;
    stage(0, 0);
    if (nch > 1) stage(1, GK);

    const int rowA = wm * 64 + g;      // +mt*16 / +8 per fragment
    const int colB = wn * 64 + g;      // +nt*8

    for (int i = 0; i < nch; i++) {
        const int buf = i % NSTAGE;
        if (i + 1 < nch) { CP_WAIT(1); } else { CP_WAIT(0); }
        __syncthreads();
        if (i + 2 < nch) stage((i + 2) % NSTAGE, (i + 2) * GK);

        const uint32_t* As = (const uint32_t*)(smem + buf * BUF_BYTES);
        const uint32_t* Bs = (const uint32_t*)(smem + buf * BUF_BYTES + TILE_B);

#pragma unroll
        for (int step = 0; step < 4; step++) {
            const int c0   = step * 2;
            const int off0 = (((c0    ) ^ g) << 2) + tg;
            const int off1 = (((c0 + 1) ^ g) << 2) + tg;

            uint32_t a[4][4];
#pragma unroll
            for (int mt = 0; mt < 4; mt++) {
                const int b0 = (rowA + mt * 16) * 32;
                a[mt][0] = As[b0 + off0];
                a[mt][1] = As[b0 + 8 * 32 + off0];
                a[mt][2] = As[b0 + off1];
                a[mt][3] = As[b0 + 8 * 32 + off1];
            }
            uint32_t b[8][2];
#pragma unroll
            for (int nt = 0; nt < 8; nt++) {
                const int bb = (colB + nt * 8) * 32;
                b[nt][0] = Bs[bb + off0];
                b[nt][1] = Bs[bb + off1];
            }
#pragma unroll
            for (int mt = 0; mt < 4; mt++)
#pragma unroll
                for (int nt = 0; nt < 8; nt++)
                    mma_tf32(acc[mt][nt], a[mt], b[nt]);
        }
    }

    // Epilogue: fragment (mt,nt): rows r0, r0+8 ; cols col, col+1
#pragma unroll
    for (int mt = 0; mt < 4; mt++) {
        const int r0 = m0 + wm * 64 + mt * 16 + g;
#pragma unroll
        for (int nt = 0; nt < 8; nt++) {
            const int col = n0 + wn * 64 + nt * 8 + tg * 2;
            float v0 = acc[mt][nt][0], v1 = acc[mt][nt][1];
            float v2 = acc[mt][nt][2], v3 = acc[mt][nt][3];
            if (MODE == 1) {
                v0 = selu_f(v0 + bias[col]);     v1 = selu_f(v1 + bias[col + 1]);
                v2 = selu_f(v2 + bias[col]);     v3 = selu_f(v3 + bias[col + 1]);
            }
            if (MODE == 2) {
                const float b0v = bias[col], b1v = bias[col + 1];
                v0 += b0v + res[(size_t)r0 * N + col];
                v1 += b1v + res[(size_t)r0 * N + col + 1];
                v2 += b0v + res[(size_t)(r0 + 8) * N + col];
                v3 += b1v + res[(size_t)(r0 + 8) * N + col + 1];
            }
            *(float2*)&C[(size_t)r0 * N + col]       = make_float2(v0, v1);
            *(float2*)&C[(size_t)(r0 + 8) * N + col] = make_float2(v2, v3);
        }
    }
}

// ---------------------------------------------------------------------------
// Tensor-core flash attention (unchanged from R5).
// ---------------------------------------------------------------------------
#define SQK 68
#define SV  72
#define ATT_SMEM ((4*64*SQK + 64*SV) * 4)   // 88064 B

__global__ __launch_bounds__(128)
void attn_tc(const float* __restrict__ Q, const float* __restrict__ K,
             const float* __restrict__ V, float* __restrict__ O)
{
    extern __shared__ float sm[];
    float* Qh = sm;
    float* Ql = Qh + 64*SQK;
    float* Kh = Ql + 64*SQK;
    float* Kl = Kh + 64*SQK;
    float* Vs = Kl + 64*SQK;

    const int qb = (int)gridDim.x - 1 - (int)blockIdx.x;  // heavy blocks first
    const int q0 = qb * 64;
    const int bh = blockIdx.y;
    const int b  = bh >> 4;
    const int h  = bh & 15;
    const size_t base = (size_t)b * LL * DD + (size_t)h * DH;

    const int tid  = threadIdx.x;
    const int w    = tid >> 5;
    const int lane = tid & 31;
    const int g    = lane >> 2;
    const int tg   = lane & 3;
    const int qw   = w * 16;

#pragma unroll
    for (int i = 0; i < 8; i++) {
        int idx = tid + i * 128;
        int r = idx >> 4, c4 = (idx & 15) * 4;
        float4 v = *(const float4*)&Q[base + (size_t)(q0 + r) * DD + c4];
        v.x *= 0.125f; v.y *= 0.125f; v.z *= 0.125f; v.w *= 0.125f;
        float4 hi, lo;
        hi.x = tf32r(v.x); lo.x = v.x - hi.x;
        hi.y = tf32r(v.y); lo.y = v.y - hi.y;
        hi.z = tf32r(v.z); lo.z = v.z - hi.z;
        hi.w = tf32r(v.w); lo.w = v.w - hi.w;
        *(float4*)&Qh[r * SQK + c4] = hi;
        *(float4*)&Ql[r * SQK + c4] = lo;
    }

    float m0r = -1e30f, m1r = -1e30f, l0r = 0.f, l1r = 0.f;
    float oacc[8][4];
#pragma unroll
    for (int nb = 0; nb < 8; nb++)
#pragma unroll
        for (int r = 0; r < 4; r++) oacc[nb][r] = 0.f;

    const int ntile = qb + 1;
    for (int kt = 0; kt < ntile; kt++) {
        const int k0 = kt * 64;
        __syncthreads();
#pragma unroll
        for (int i = 0; i < 8; i++) {
            int idx = tid + i * 128;
            int r = idx >> 4, c4 = (idx & 15) * 4;
            float4 kv = *(const float4*)&K[base + (size_t)(k0 + r) * DD + c4];
            float4 hi, lo;
            hi.x = tf32r(kv.x); lo.x = kv.x - hi.x;
            hi.y = tf32r(kv.y); lo.y = kv.y - hi.y;
            hi.z = tf32r(kv.z); lo.z = kv.z - hi.z;
            hi.w = tf32r(kv.w); lo.w = kv.w - hi.w;
            *(float4*)&Kh[r * SQK + c4] = hi;
            *(float4*)&Kl[r * SQK + c4] = lo;
            float4 vv = *(const float4*)&V[base + (size_t)(k0 + r) * DD + c4];
            *(float4*)&Vs[r * SV + c4] = vv;
        }
        __syncthreads();

        float sacc[8][4];
#pragma unroll
        for (int nb = 0; nb < 8; nb++)
#pragma unroll
            for (int r = 0; r < 4; r++) sacc[nb][r] = 0.f;

#pragma unroll
        for (int ks = 0; ks < 8; ks++) {
            const int d0 = ks * 8 + tg;
            uint32_t ah[4], al[4];
            ah[0] = __float_as_uint(Qh[(qw + g    ) * SQK + d0    ]);
            ah[1] = __float_as_uint(Qh[(qw + g + 8) * SQK + d0    ]);
            ah[2] = __float_as_uint(Qh[(qw + g    ) * SQK + d0 + 4]);
            ah[3] = __float_as_uint(Qh[(qw + g + 8) * SQK + d0 + 4]);
            al[0] = __float_as_uint(Ql[(qw + g    ) * SQK + d0    ]);
            al[1] = __float_as_uint(Ql[(qw + g + 8) * SQK + d0    ]);
            al[2] = __float_as_uint(Ql[(qw + g    ) * SQK + d0 + 4]);
            al[3] = __float_as_uint(Ql[(qw + g + 8) * SQK + d0 + 4]);
#pragma unroll
            for (int nb = 0; nb < 8; nb++) {
                uint32_t bh2[2], bl2[2];
                bh2[0] = __float_as_uint(Kh[(nb * 8 + g) * SQK + d0    ]);
                bh2[1] = __float_as_uint(Kh[(nb * 8 + g) * SQK + d0 + 4]);
                bl2[0] = __float_as_uint(Kl[(nb * 8 + g) * SQK + d0    ]);
                bl2[1] = __float_as_uint(Kl[(nb * 8 + g) * SQK + d0 + 4]);
                mma_tf32(sacc[nb], ah, bh2);
                mma_tf32(sacc[nb], ah, bl2);
                mma_tf32(sacc[nb], al, bh2);
            }
        }

        if (k0 == q0) {
#pragma unroll
            for (int nb = 0; nb < 8; nb++) {
                const int col = nb * 8 + 2 * tg;
                const int r0 = qw + g, r1 = r0 + 8;
                if (col     > r0) sacc[nb][0] = -1e30f;
                if (col + 1 > r0) sacc[nb][1] = -1e30f;
                if (col     > r1) sacc[nb][2] = -1e30f;
                if (col + 1 > r1) sacc[nb][3] = -1e30f;
            }
        }

        float mx0 = -1e30f, mx1 = -1e30f;
#pragma unroll
        for (int nb = 0; nb < 8; nb++) {
            mx0 = fmaxf(mx0, fmaxf(sacc[nb][0], sacc[nb][1]));
            mx1 = fmaxf(mx1, fmaxf(sacc[nb][2], sacc[nb][3]));
        }
        mx0 = fmaxf(mx0, __shfl_xor_sync(0xffffffffu, mx0, 1));
        mx0 = fmaxf(mx0, __shfl_xor_sync(0xffffffffu, mx0, 2));
        mx1 = fmaxf(mx1, __shfl_xor_sync(0xffffffffu, mx1, 1));
        mx1 = fmaxf(mx1, __shfl_xor_sync(0xffffffffu, mx1, 2));

        const float nm0 = fmaxf(m0r, mx0), nm1 = fmaxf(m1r, mx1);
        const float al0 = __expf(m0r - nm0), al1 = __expf(m1r - nm1);
        float rs0 = 0.f, rs1 = 0.f;
#pragma unroll
        for (int nb = 0; nb < 8; nb++) {
            sacc[nb][0] = __expf(sacc[nb][0] - nm0);
            sacc[nb][1] = __expf(sacc[nb][1] - nm0);
            sacc[nb][2] = __expf(sacc[nb][2] - nm1);
            sacc[nb][3] = __expf(sacc[nb][3] - nm1);
            rs0 += sacc[nb][0] + sacc[nb][1];
            rs1 += sacc[nb][2] + sacc[nb][3];
        }
        rs0 += __shfl_xor_sync(0xffffffffu, rs0, 1);
        rs0 += __shfl_xor_sync(0xffffffffu, rs0, 2);
        rs1 += __shfl_xor_sync(0xffffffffu, rs1, 1);
        rs1 += __shfl_xor_sync(0xffffffffu, rs1, 2);
        l0r = l0r * al0 + rs0;
        l1r = l1r * al1 + rs1;
        m0r = nm0; m1r = nm1;
#pragma unroll
        for (int nb = 0; nb < 8; nb++) {
            oacc[nb][0] *= al0; oacc[nb][1] *= al0;
            oacc[nb][2] *= al1; oacc[nb][3] *= al1;
        }

#pragma unroll
        for (int ks2 = 0; ks2 < 8; ks2++) {
            const int sA = (lane & 28) | (tg >> 1);
            const int sB = sA + 2;
            const float q0v = __shfl_sync(0xffffffffu, sacc[ks2][0], sA);
            const float q1v = __shfl_sync(0xffffffffu, sacc[ks2][1], sA);
            const float q2v = __shfl_sync(0xffffffffu, sacc[ks2][2], sA);
            const float q3v = __shfl_sync(0xffffffffu, sacc[ks2][3], sA);
            const float r0v = __shfl_sync(0xffffffffu, sacc[ks2][0], sB);
            const float r1v = __shfl_sync(0xffffffffu, sacc[ks2][1], sB);
            const float r2v = __shfl_sync(0xffffffffu, sacc[ks2][2], sB);
            const float r3v = __shfl_sync(0xffffffffu, sacc[ks2][3], sB);
            const bool oddc = (tg & 1);
            uint32_t aP[4];
            aP[0] = __float_as_uint(oddc ? q1v : q0v);
            aP[1] = __float_as_uint(oddc ? q3v : q2v);
            aP[2] = __float_as_uint(oddc ? r1v : r0v);
            aP[3] = __float_as_uint(oddc ? r3v : r2v);
#pragma unroll
            for (int nb2 = 0; nb2 < 8; nb2++) {
                uint32_t bV[2];
                bV[0] = __float_as_uint(Vs[(ks2 * 8 + tg    ) * SV + nb2 * 8 + g]);
                bV[1] = __float_as_uint(Vs[(ks2 * 8 + tg + 4) * SV + nb2 * 8 + g]);
                mma_tf32(oacc[nb2], aP, bV);
            }
        }
    }

    const float inv0 = 1.f / l0r, inv1 = 1.f / l1r;
    const int r0 = q0 + qw + g, r1 = r0 + 8;
#pragma unroll
    for (int nb = 0; nb < 8; nb++) {
        const int c = nb * 8 + tg * 2;
        *(float2*)&O[base + (size_t)r0 * DD + c] =
            make_float2(oacc[nb][0] * inv0, oacc[nb][1] * inv0);
        *(float2*)&O[base + (size_t)r1 * DD + c] =
            make_float2(oacc[nb][2] * inv1, oacc[nb][3] * inv1);
    }
}

// ---------------------------------------------------------------------------
// LayerNorm over last dim (1024), optional residual (unchanged).
// ---------------------------------------------------------------------------
__global__ __launch_bounds__(256)
void ln_kernel(const float* __restrict__ x, const float* __restrict__ add,
               const float* __restrict__ g, const float* __restrict__ bta,
               float* __restrict__ out)
{
    const int row = blockIdx.x;
    const int tid = threadIdx.x;
    const size_t off = (size_t)row * DD + tid * 4;

    float4 v = *(const float4*)&x[off];
    if (add != nullptr) {
        float4 a = *(const float4*)&add[off];
        v.x += a.x; v.y += a.y; v.z += a.z; v.w += a.w;
    }
    float s1 = v.x + v.y + v.z + v.w;
    float s2 = v.x*v.x + v.y*v.y + v.z*v.z + v.w*v.w;
#pragma unroll
    for (int o2 = 16; o2; o2 >>= 1) {
        s1 += __shfl_xor_sync(0xffffffffu, s1, o2);
        s2 += __shfl_xor_sync(0xffffffffu, s2, o2);
    }
    __shared__ float r1[8], r2[8], mb[2];
    const int lane = tid & 31, wd = tid >> 5;
    if (lane == 0) { r1[wd] = s1; r2[wd] = s2; }
    __syncthreads();
    if (tid == 0) {
        float a = 0.f, c = 0.f;
#pragma unroll
        for (int w = 0; w < 8; w++) { a += r1[w]; c += r2[w]; }
        const float mean = a * (1.f / DD);
        const float var  = c * (1.f / DD) - mean * mean;
        mb[0] = mean;
        mb[1] = rsqrtf(var + 1e-5f);
    }
    __syncthreads();
    const float mean = mb[0], rstd = mb[1];

    float4 gg = *(const float4*)&g[tid * 4];
    float4 bb = *(const float4*)&bta[tid * 4];
    float4 r;
    r.x = (v.x - mean) * rstd * gg.x + bb.x;
    r.y = (v.y - mean) * rstd * gg.y + bb.y;
    r.z = (v.z - mean) * rstd * gg.z + bb.z;
    r.w = (v.w - mean) * rstd * gg.w + bb.w;
    *(float4*)&out[off] = r;
}

// ---------------------------------------------------------------------------
extern "C" void kernel_launch(void* const* d_in, const int* in_sizes, int n_in,
                              void* d_out, int out_size)
{
    const float* X     = (const float*)d_in[0];
    const float* wq    = (const float*)d_in[1];
    const float* wk    = (const float*)d_in[2];
    const float* wv    = (const float*)d_in[3];
    const float* ln1_g = (const float*)d_in[4];
    const float* ln1_b = (const float*)d_in[5];
    const float* w1    = (const float*)d_in[6];
    const float* b1    = (const float*)d_in[7];
    const float* w2    = (const float*)d_in[8];
    const float* b2    = (const float*)d_in[9];
    const float* ln2_g = (const float*)d_in[10];
    const float* ln2_b = (const float*)d_in[11];
    float* out = (float*)d_out;

    float *pQ, *pK, *pV, *pCtx, *pX1, *pHb, *pY;
    cudaGetSymbolAddress((void**)&pQ,   g_Q);
    cudaGetSymbolAddress((void**)&pK,   g_K);
    cudaGetSymbolAddress((void**)&pV,   g_V);
    cudaGetSymbolAddress((void**)&pCtx, g_ctx);
    cudaGetSymbolAddress((void**)&pX1,  g_X1);
    cudaGetSymbolAddress((void**)&pHb,  g_Hb);
    cudaGetSymbolAddress((void**)&pY,   g_Y);

    cudaFuncSetAttribute(gemm_mma<1>, cudaFuncAttributeMaxDynamicSharedMemorySize, GEMM_SMEM);
    cudaFuncSetAttribute(gemm_mma<2>, cudaFuncAttributeMaxDynamicSharedMemorySize, GEMM_SMEM);
    cudaFuncSetAttribute(gemm_mma<3>, cudaFuncAttributeMaxDynamicSharedMemorySize, GEMM_SMEM);
    cudaFuncSetAttribute(attn_tc,     cudaFuncAttributeMaxDynamicSharedMemorySize, ATT_SMEM);

    const dim3 blk(128);
    // Fused QKV projection (blockIdx.z selects weight/output)
    gemm_mma<3><<<dim3(DD/128, MM/128, 3), blk, GEMM_SMEM>>>(
        X, wq, wk, wv, pQ, pK, pV, nullptr, nullptr, MM, DD, DD);
    attn_tc<<<dim3(LL/64, BB*HH), 128, ATT_SMEM>>>(pQ, pK, pV, pCtx);
    ln_kernel<<<MM, 256>>>(X, pCtx, ln1_g, ln1_b, pX1);
    gemm_mma<1><<<dim3(DFF/128, MM/128), blk, GEMM_SMEM>>>(
        pX1, w1, nullptr, nullptr, pHb, nullptr, nullptr, b1, nullptr, MM, DFF, DD);
    gemm_mma<2><<<dim3(DD/128,  MM/128), blk, GEMM_SMEM>>>(
        pHb, w2, nullptr, nullptr, pY, nullptr, nullptr, b2, pX1, MM, DD, DFF);
    ln_kernel<<<MM, 256>>>(pY, nullptr, ln2_g, ln2_b, out);
}

// round 8
// speedup vs baseline: 4.1544x; 1.0590x over previous
#include <cuda_runtime.h>
#include <cstdint>
#include <math.h>

// DecoderLayer fwd: B=4, L=1024, D=1024, H=16, dh=64, Dff=4096, fp32 I/O.
// R7: GEMM inner loop gets explicit fragment double-buffering (hide LDS lat);
//     FFN2 split-K=2 (grid 256->512) with reduction fused into LN2.
//     Attention unchanged from R5/R6.

#define BB  4
#define LL  1024
#define DD  1024
#define HH  16
#define DH  64
#define DFF 4096
#define MM  (BB*LL)   // 4096

// Scratch (allocation-free: __device__ globals)
__device__ float g_Q[MM*DD];
__device__ float g_K[MM*DD];
__device__ float g_V[MM*DD];
__device__ float g_ctx[MM*DD];
__device__ float g_X1[MM*DD];
__device__ float g_Hb[(size_t)MM*DFF];
__device__ float g_Y[MM*DD];
__device__ float g_Y2[MM*DD];

static __device__ __forceinline__ float selu_f(float x) {
    const float scale = 1.0507009873554804934193349852946f;
    const float alpha = 1.6732632423543772848170429916717f;
    return x > 0.f ? scale * x : scale * alpha * (__expf(x) - 1.f);
}

static __device__ __forceinline__ uint32_t smem_u32(const void* p) {
    uint32_t a;
    asm("{ .reg .u64 t; cvta.to.shared.u64 t, %1; cvt.u32.u64 %0, t; }"
        : "=r"(a) : "l"(p));
    return a;
}

#define CP16(dst, src) \
    asm volatile("cp.async.cg.shared.global [%0], [%1], 16;" \
                 :: "r"((uint32_t)(dst)), "l"(src) : "memory")
#define CP_COMMIT() asm volatile("cp.async.commit_group;" ::: "memory")
#define CP_WAIT(n)  asm volatile("cp.async.wait_group %0;" :: "n"(n) : "memory")

static __device__ __forceinline__ void mma_tf32(float* c, const uint32_t* a,
                                                const uint32_t* b) {
    asm volatile(
        "mma.sync.aligned.m16n8k8.row.col.f32.tf32.tf32.f32 "
        "{%0,%1,%2,%3}, {%4,%5,%6,%7}, {%8,%9}, {%0,%1,%2,%3};"
        : "+f"(c[0]), "+f"(c[1]), "+f"(c[2]), "+f"(c[3])
        : "r"(a[0]), "r"(a[1]), "r"(a[2]), "r"(a[3]), "r"(b[0]), "r"(b[1]));
}

static __device__ __forceinline__ float tf32r(float x) {
    uint32_t u;
    asm("cvt.rna.tf32.f32 %0, %1;" : "=r"(u) : "f"(x));
    return __uint_as_float(u);
}

// ---------------------------------------------------------------------------
// tf32 mma.sync GEMM: C[M,N] = A[M,K] @ B[N,K]^T  (torch Linear layout)
// CTA 128x128, BK=32, 128 threads = 4 warps (2Mx2N), warp tile 64x64.
// 3-stage cp.async pipeline + explicit fragment double-buffering.
// MODE 1: C = selu(acc+bias)
// MODE 3: QKV — blockIdx.z selects (B0,C0)/(B1,C1)/(B2,C2), plain store.
// MODE 4: split-K(2) — blockIdx.z selects k-half and C0/C1, plain store.
// ---------------------------------------------------------------------------
#define GK        32
#define TILE_B    16384                 // 128 rows * 32 floats * 4B
#define BUF_BYTES (2 * TILE_B)          // A + B per stage
#define NSTAGE    3
#define GEMM_SMEM (NSTAGE * BUF_BYTES)  // 98304

template<int MODE>
__global__ __launch_bounds__(128, 2)
void gemm_mma(const float* __restrict__ A,
              const float* __restrict__ B0, const float* __restrict__ B1,
              const float* __restrict__ B2,
              float* __restrict__ C0, float* __restrict__ C1,
              float* __restrict__ C2,
              const float* __restrict__ bias,
              int M, int N, int K)
{
    extern __shared__ char smem[];
    const uint32_t sb = smem_u32(smem);
    const int tid  = threadIdx.x;
    const int wid  = tid >> 5;
    const int lane = tid & 31;
    const int g    = lane >> 2;
    const int tg   = lane & 3;
    const int wm   = wid & 1;          // 2 warps in M
    const int wn   = wid >> 1;         // 2 warps in N
    const int m0   = blockIdx.y * 128;
    const int n0   = blockIdx.x * 128;

    const float* Bw = B0;
    float*       C  = C0;
    if (MODE == 3) {
        if (blockIdx.z == 1)      { Bw = B1; C = C1; }
        else if (blockIdx.z == 2) { Bw = B2; C = C2; }
    }
    int keff = K, koff = 0;
    if (MODE == 4) {
        keff = K >> 1;
        koff = blockIdx.z * keff;
        if (blockIdx.z == 1) C = C1;
    }

    auto stage = [&](int s, int k0) {
        const uint32_t ab = sb + s * BUF_BYTES;
#pragma unroll
        for (int t = 0; t < 8; t++) {
            int idx = tid + t * 128;               // 0..1023
            int row = idx >> 3;                    // 0..127
            int c   = idx & 7;                     // 16B chunk
            uint32_t off = row * 128 + (((uint32_t)(c ^ (row & 7))) << 4);
            CP16(ab + off,          A  + (size_t)(m0 + row) * K + koff + k0 + c * 4);
            CP16(ab + TILE_B + off, Bw + (size_t)(n0 + row) * K + koff + k0 + c * 4);
        }
        CP_COMMIT();
    };

    const int rowA = wm * 64 + g;
    const int colB = wn * 64 + g;

    auto loadA = [&](const uint32_t* As, int step, uint32_t a[4][4]) {
        const int c0   = step * 2;
        const int off0 = (((c0    ) ^ g) << 2) + tg;
        const int off1 = (((c0 + 1) ^ g) << 2) + tg;
#pragma unroll
        for (int mt = 0; mt < 4; mt++) {
            const int b0 = (rowA + mt * 16) * 32;
            a[mt][0] = As[b0 + off0];
            a[mt][1] = As[b0 + 8 * 32 + off0];
            a[mt][2] = As[b0 + off1];
            a[mt][3] = As[b0 + 8 * 32 + off1];
        }
    };
    auto loadB = [&](const uint32_t* Bs, int step, uint32_t b[8][2]) {
        const int c0   = step * 2;
        const int off0 = (((c0    ) ^ g) << 2) + tg;
        const int off1 = (((c0 + 1) ^ g) << 2) + tg;
#pragma unroll
        for (int nt = 0; nt < 8; nt++) {
            const int bb = (colB + nt * 8) * 32;
            b[nt][0] = Bs[bb + off0];
            b[nt][1] = Bs[bb + off1];
        }
    };

    float acc[4][8][4];
#pragma unroll
    for (int mt = 0; mt < 4; mt++)
#pragma unroll
        for (int nt = 0; nt < 8; nt++)
#pragma unroll
            for (int r = 0; r < 4; r++) acc[mt][nt][r] = 0.f;

    const int nch = keff / GK;
    stage(0, 0);
    if (nch > 1) stage(1, GK);

    for (int i = 0; i < nch; i++) {
        const int buf = i % NSTAGE;
        if (i + 1 < nch) { CP_WAIT(1); } else { CP_WAIT(0); }
        __syncthreads();
        if (i + 2 < nch) stage((i + 2) % NSTAGE, (i + 2) * GK);

        const uint32_t* As = (const uint32_t*)(smem + buf * BUF_BYTES);
        const uint32_t* Bs = (const uint32_t*)(smem + buf * BUF_BYTES + TILE_B);

        uint32_t af[2][4][4], bf[2][8][2];
        loadA(As, 0, af[0]);
        loadB(Bs, 0, bf[0]);
#pragma unroll
        for (int step = 0; step < 4; step++) {
            const int cur = step & 1, nxt = cur ^ 1;
            if (step < 3) {
                loadA(As, step + 1, af[nxt]);
                loadB(Bs, step + 1, bf[nxt]);
            }
#pragma unroll
            for (int mt = 0; mt < 4; mt++)
#pragma unroll
                for (int nt = 0; nt < 8; nt++)
                    mma_tf32(acc[mt][nt], af[cur][mt], bf[cur][nt]);
        }
    }

    // Epilogue: fragment (mt,nt): rows r0, r0+8 ; cols col, col+1
#pragma unroll
    for (int mt = 0; mt < 4; mt++) {
        const int r0 = m0 + wm * 64 + mt * 16 + g;
#pragma unroll
        for (int nt = 0; nt < 8; nt++) {
            const int col = n0 + wn * 64 + nt * 8 + tg * 2;
            float v0 = acc[mt][nt][0], v1 = acc[mt][nt][1];
            float v2 = acc[mt][nt][2], v3 = acc[mt][nt][3];
            if (MODE == 1) {
                v0 = selu_f(v0 + bias[col]);     v1 = selu_f(v1 + bias[col + 1]);
                v2 = selu_f(v2 + bias[col]);     v3 = selu_f(v3 + bias[col + 1]);
            }
            *(float2*)&C[(size_t)r0 * N + col]       = make_float2(v0, v1);
            *(float2*)&C[(size_t)(r0 + 8) * N + col] = make_float2(v2, v3);
        }
    }
}

// ---------------------------------------------------------------------------
// Tensor-core flash attention (unchanged from R5/R6).
// ---------------------------------------------------------------------------
#define SQK 68
#define SV  72
#define ATT_SMEM ((4*64*SQK + 64*SV) * 4)   // 88064 B

__global__ __launch_bounds__(128)
void attn_tc(const float* __restrict__ Q, const float* __restrict__ K,
             const float* __restrict__ V, float* __restrict__ O)
{
    extern __shared__ float sm[];
    float* Qh = sm;
    float* Ql = Qh + 64*SQK;
    float* Kh = Ql + 64*SQK;
    float* Kl = Kh + 64*SQK;
    float* Vs = Kl + 64*SQK;

    const int qb = (int)gridDim.x - 1 - (int)blockIdx.x;
    const int q0 = qb * 64;
    const int bh = blockIdx.y;
    const int b  = bh >> 4;
    const int h  = bh & 15;
    const size_t base = (size_t)b * LL * DD + (size_t)h * DH;

    const int tid  = threadIdx.x;
    const int w    = tid >> 5;
    const int lane = tid & 31;
    const int g    = lane >> 2;
    const int tg   = lane & 3;
    const int qw   = w * 16;

#pragma unroll
    for (int i = 0; i < 8; i++) {
        int idx = tid + i * 128;
        int r = idx >> 4, c4 = (idx & 15) * 4;
        float4 v = *(const float4*)&Q[base + (size_t)(q0 + r) * DD + c4];
        v.x *= 0.125f; v.y *= 0.125f; v.z *= 0.125f; v.w *= 0.125f;
        float4 hi, lo;
        hi.x = tf32r(v.x); lo.x = v.x - hi.x;
        hi.y = tf32r(v.y); lo.y = v.y - hi.y;
        hi.z = tf32r(v.z); lo.z = v.z - hi.z;
        hi.w = tf32r(v.w); lo.w = v.w - hi.w;
        *(float4*)&Qh[r * SQK + c4] = hi;
        *(float4*)&Ql[r * SQK + c4] = lo;
    }

    float m0r = -1e30f, m1r = -1e30f, l0r = 0.f, l1r = 0.f;
    float oacc[8][4];
#pragma unroll
    for (int nb = 0; nb < 8; nb++)
#pragma unroll
        for (int r = 0; r < 4; r++) oacc[nb][r] = 0.f;

    const int ntile = qb + 1;
    for (int kt = 0; kt < ntile; kt++) {
        const int k0 = kt * 64;
        __syncthreads();
#pragma unroll
        for (int i = 0; i < 8; i++) {
            int idx = tid + i * 128;
            int r = idx >> 4, c4 = (idx & 15) * 4;
            float4 kv = *(const float4*)&K[base + (size_t)(k0 + r) * DD + c4];
            float4 hi, lo;
            hi.x = tf32r(kv.x); lo.x = kv.x - hi.x;
            hi.y = tf32r(kv.y); lo.y = kv.y - hi.y;
            hi.z = tf32r(kv.z); lo.z = kv.z - hi.z;
            hi.w = tf32r(kv.w); lo.w = kv.w - hi.w;
            *(float4*)&Kh[r * SQK + c4] = hi;
            *(float4*)&Kl[r * SQK + c4] = lo;
            float4 vv = *(const float4*)&V[base + (size_t)(k0 + r) * DD + c4];
            *(float4*)&Vs[r * SV + c4] = vv;
        }
        __syncthreads();

        float sacc[8][4];
#pragma unroll
        for (int nb = 0; nb < 8; nb++)
#pragma unroll
            for (int r = 0; r < 4; r++) sacc[nb][r] = 0.f;

#pragma unroll
        for (int ks = 0; ks < 8; ks++) {
            const int d0 = ks * 8 + tg;
            uint32_t ah[4], al[4];
            ah[0] = __float_as_uint(Qh[(qw + g    ) * SQK + d0    ]);
            ah[1] = __float_as_uint(Qh[(qw + g + 8) * SQK + d0    ]);
            ah[2] = __float_as_uint(Qh[(qw + g    ) * SQK + d0 + 4]);
            ah[3] = __float_as_uint(Qh[(qw + g + 8) * SQK + d0 + 4]);
            al[0] = __float_as_uint(Ql[(qw + g    ) * SQK + d0    ]);
            al[1] = __float_as_uint(Ql[(qw + g + 8) * SQK + d0    ]);
            al[2] = __float_as_uint(Ql[(qw + g    ) * SQK + d0 + 4]);
            al[3] = __float_as_uint(Ql[(qw + g + 8) * SQK + d0 + 4]);
#pragma unroll
            for (int nb = 0; nb < 8; nb++) {
                uint32_t bh2[2], bl2[2];
                bh2[0] = __float_as_uint(Kh[(nb * 8 + g) * SQK + d0    ]);
                bh2[1] = __float_as_uint(Kh[(nb * 8 + g) * SQK + d0 + 4]);
                bl2[0] = __float_as_uint(Kl[(nb * 8 + g) * SQK + d0    ]);
                bl2[1] = __float_as_uint(Kl[(nb * 8 + g) * SQK + d0 + 4]);
                mma_tf32(sacc[nb], ah, bh2);
                mma_tf32(sacc[nb], ah, bl2);
                mma_tf32(sacc[nb], al, bh2);
            }
        }

        if (k0 == q0) {
#pragma unroll
            for (int nb = 0; nb < 8; nb++) {
                const int col = nb * 8 + 2 * tg;
                const int r0 = qw + g, r1 = r0 + 8;
                if (col     > r0) sacc[nb][0] = -1e30f;
                if (col + 1 > r0) sacc[nb][1] = -1e30f;
                if (col     > r1) sacc[nb][2] = -1e30f;
                if (col + 1 > r1) sacc[nb][3] = -1e30f;
            }
        }

        float mx0 = -1e30f, mx1 = -1e30f;
#pragma unroll
        for (int nb = 0; nb < 8; nb++) {
            mx0 = fmaxf(mx0, fmaxf(sacc[nb][0], sacc[nb][1]));
            mx1 = fmaxf(mx1, fmaxf(sacc[nb][2], sacc[nb][3]));
        }
        mx0 = fmaxf(mx0, __shfl_xor_sync(0xffffffffu, mx0, 1));
        mx0 = fmaxf(mx0, __shfl_xor_sync(0xffffffffu, mx0, 2));
        mx1 = fmaxf(mx1, __shfl_xor_sync(0xffffffffu, mx1, 1));
        mx1 = fmaxf(mx1, __shfl_xor_sync(0xffffffffu, mx1, 2));

        const float nm0 = fmaxf(m0r, mx0), nm1 = fmaxf(m1r, mx1);
        const float al0 = __expf(m0r - nm0), al1 = __expf(m1r - nm1);
        float rs0 = 0.f, rs1 = 0.f;
#pragma unroll
        for (int nb = 0; nb < 8; nb++) {
            sacc[nb][0] = __expf(sacc[nb][0] - nm0);
            sacc[nb][1] = __expf(sacc[nb][1] - nm0);
            sacc[nb][2] = __expf(sacc[nb][2] - nm1);
            sacc[nb][3] = __expf(sacc[nb][3] - nm1);
            rs0 += sacc[nb][0] + sacc[nb][1];
            rs1 += sacc[nb][2] + sacc[nb][3];
        }
        rs0 += __shfl_xor_sync(0xffffffffu, rs0, 1);
        rs0 += __shfl_xor_sync(0xffffffffu, rs0, 2);
        rs1 += __shfl_xor_sync(0xffffffffu, rs1, 1);
        rs1 += __shfl_xor_sync(0xffffffffu, rs1, 2);
        l0r = l0r * al0 + rs0;
        l1r = l1r * al1 + rs1;
        m0r = nm0; m1r = nm1;
#pragma unroll
        for (int nb = 0; nb < 8; nb++) {
            oacc[nb][0] *= al0; oacc[nb][1] *= al0;
            oacc[nb][2] *= al1; oacc[nb][3] *= al1;
        }

#pragma unroll
        for (int ks2 = 0; ks2 < 8; ks2++) {
            const int sA = (lane & 28) | (tg >> 1);
            const int sB = sA + 2;
            const float q0v = __shfl_sync(0xffffffffu, sacc[ks2][0], sA);
            const float q1v = __shfl_sync(0xffffffffu, sacc[ks2][1], sA);
            const float q2v = __shfl_sync(0xffffffffu, sacc[ks2][2], sA);
            const float q3v = __shfl_sync(0xffffffffu, sacc[ks2][3], sA);
            const float r0v = __shfl_sync(0xffffffffu, sacc[ks2][0], sB);
            const float r1v = __shfl_sync(0xffffffffu, sacc[ks2][1], sB);
            const float r2v = __shfl_sync(0xffffffffu, sacc[ks2][2], sB);
            const float r3v = __shfl_sync(0xffffffffu, sacc[ks2][3], sB);
            const bool oddc = (tg & 1);
            uint32_t aP[4];
            aP[0] = __float_as_uint(oddc ? q1v : q0v);
            aP[1] = __float_as_uint(oddc ? q3v : q2v);
            aP[2] = __float_as_uint(oddc ? r1v : r0v);
            aP[3] = __float_as_uint(oddc ? r3v : r2v);
#pragma unroll
            for (int nb2 = 0; nb2 < 8; nb2++) {
                uint32_t bV[2];
                bV[0] = __float_as_uint(Vs[(ks2 * 8 + tg    ) * SV + nb2 * 8 + g]);
                bV[1] = __float_as_uint(Vs[(ks2 * 8 + tg + 4) * SV + nb2 * 8 + g]);
                mma_tf32(oacc[nb2], aP, bV);
            }
        }
    }

    const float inv0 = 1.f / l0r, inv1 = 1.f / l1r;
    const int r0 = q0 + qw + g, r1 = r0 + 8;
#pragma unroll
    for (int nb = 0; nb < 8; nb++) {
        const int c = nb * 8 + tg * 2;
        *(float2*)&O[base + (size_t)r0 * DD + c] =
            make_float2(oacc[nb][0] * inv0, oacc[nb][1] * inv0);
        *(float2*)&O[base + (size_t)r1 * DD + c] =
            make_float2(oacc[nb][2] * inv1, oacc[nb][3] * inv1);
    }
}

// ---------------------------------------------------------------------------
// LayerNorm over last dim (1024). Input = x [+ add] [+ add2] [+ brow[col]].
// grid = 4096 rows, block = 256.
// ---------------------------------------------------------------------------
__global__ __launch_bounds__(256)
void ln_kernel(const float* __restrict__ x, const float* __restrict__ add,
               const float* __restrict__ add2, const float* __restrict__ brow,
               const float* __restrict__ g, const float* __restrict__ bta,
               float* __restrict__ out)
{
    const int row = blockIdx.x;
    const int tid = threadIdx.x;
    const size_t off = (size_t)row * DD + tid * 4;

    float4 v = *(const float4*)&x[off];
    if (add != nullptr) {
        float4 a = *(const float4*)&add[off];
        v.x += a.x; v.y += a.y; v.z += a.z; v.w += a.w;
    }
    if (add2 != nullptr) {
        float4 a = *(const float4*)&add2[off];
        v.x += a.x; v.y += a.y; v.z += a.z; v.w += a.w;
    }
    if (brow != nullptr) {
        float4 a = *(const float4*)&brow[tid * 4];
        v.x += a.x; v.y += a.y; v.z += a.z; v.w += a.w;
    }
    float s1 = v.x + v.y + v.z + v.w;
    float s2 = v.x*v.x + v.y*v.y + v.z*v.z + v.w*v.w;
#pragma unroll
    for (int o2 = 16; o2; o2 >>= 1) {
        s1 += __shfl_xor_sync(0xffffffffu, s1, o2);
        s2 += __shfl_xor_sync(0xffffffffu, s2, o2);
    }
    __shared__ float r1[8], r2[8], mb[2];
    const int lane = tid & 31, wd = tid >> 5;
    if (lane == 0) { r1[wd] = s1; r2[wd] = s2; }
    __syncthreads();
    if (tid == 0) {
        float a = 0.f, c = 0.f;
#pragma unroll
        for (int w = 0; w < 8; w++) { a += r1[w]; c += r2[w]; }
        const float mean = a * (1.f / DD);
        const float var  = c * (1.f / DD) - mean * mean;
        mb[0] = mean;
        mb[1] = rsqrtf(var + 1e-5f);
    }
    __syncthreads();
    const float mean = mb[0], rstd = mb[1];

    float4 gg = *(const float4*)&g[tid * 4];
    float4 bb = *(const float4*)&bta[tid * 4];
    float4 r;
    r.x = (v.x - mean) * rstd * gg.x + bb.x;
    r.y = (v.y - mean) * rstd * gg.y + bb.y;
    r.z = (v.z - mean) * rstd * gg.z + bb.z;
    r.w = (v.w - mean) * rstd * gg.w + bb.w;
    *(float4*)&out[off] = r;
}

// ---------------------------------------------------------------------------
extern "C" void kernel_launch(void* const* d_in, const int* in_sizes, int n_in,
                              void* d_out, int out_size)
{
    const float* X     = (const float*)d_in[0];
    const float* wq    = (const float*)d_in[1];
    const float* wk    = (const float*)d_in[2];
    const float* wv    = (const float*)d_in[3];
    const float* ln1_g = (const float*)d_in[4];
    const float* ln1_b = (const float*)d_in[5];
    const float* w1    = (const float*)d_in[6];
    const float* b1    = (const float*)d_in[7];
    const float* w2    = (const float*)d_in[8];
    const float* b2    = (const float*)d_in[9];
    const float* ln2_g = (const float*)d_in[10];
    const float* ln2_b = (const float*)d_in[11];
    float* out = (float*)d_out;

    float *pQ, *pK, *pV, *pCtx, *pX1, *pHb, *pY, *pY2;
    cudaGetSymbolAddress((void**)&pQ,   g_Q);
    cudaGetSymbolAddress((void**)&pK,   g_K);
    cudaGetSymbolAddress((void**)&pV,   g_V);
    cudaGetSymbolAddress((void**)&pCtx, g_ctx);
    cudaGetSymbolAddress((void**)&pX1,  g_X1);
    cudaGetSymbolAddress((void**)&pHb,  g_Hb);
    cudaGetSymbolAddress((void**)&pY,   g_Y);
    cudaGetSymbolAddress((void**)&pY2,  g_Y2);

    cudaFuncSetAttribute(gemm_mma<1>, cudaFuncAttributeMaxDynamicSharedMemorySize, GEMM_SMEM);
    cudaFuncSetAttribute(gemm_mma<3>, cudaFuncAttributeMaxDynamicSharedMemorySize, GEMM_SMEM);
    cudaFuncSetAttribute(gemm_mma<4>, cudaFuncAttributeMaxDynamicSharedMemorySize, GEMM_SMEM);
    cudaFuncSetAttribute(attn_tc,     cudaFuncAttributeMaxDynamicSharedMemorySize, ATT_SMEM);

    const dim3 blk(128);
    // Fused QKV projection (blockIdx.z selects weight/output)
    gemm_mma<3><<<dim3(DD/128, MM/128, 3), blk, GEMM_SMEM>>>(
        X, wq, wk, wv, pQ, pK, pV, nullptr, MM, DD, DD);
    attn_tc<<<dim3(LL/64, BB*HH), 128, ATT_SMEM>>>(pQ, pK, pV, pCtx);
    ln_kernel<<<MM, 256>>>(X, pCtx, nullptr, nullptr, ln1_g, ln1_b, pX1);
    // FFN up + SELU
    gemm_mma<1><<<dim3(DFF/128, MM/128), blk, GEMM_SMEM>>>(
        pX1, w1, nullptr, nullptr, pHb, nullptr, nullptr, b1, MM, DFF, DD);
    // FFN down, split-K=2 (z=0: k[0,2048) -> pY ; z=1: k[2048,4096) -> pY2)
    gemm_mma<4><<<dim3(DD/128, MM/128, 2), blk, GEMM_SMEM>>>(
        pHb, w2, nullptr, nullptr, pY, pY2, nullptr, nullptr, MM, DD, DFF);
    // LN2( Y + Y2 + X1 + b2 ) -> out
    ln_kernel<<<MM, 256>>>(pY, pY2, pX1, b2, ln2_g, ln2_b, out);
}